// round 5
// baseline (speedup 1.0000x reference)
#include <cuda_runtime.h>
#include <cuda_bf16.h>
#include <math.h>

// Problem constants (fixed shapes)
#define BB 8
#define CC 256
#define HH 56
#define WW 56
#define HWHW 3136            // 56*56
#define NPIX 25088           // B*H*W
#define NF 6422528           // B*C*H*W
#define RR 2
#define HID 64

// ---------------------------------------------------------------------------
// packed f32x2 helpers
__device__ __forceinline__ unsigned long long fma_f32x2(
    unsigned long long a, unsigned long long b, unsigned long long c)
{
    unsigned long long d;
    asm("fma.rn.f32x2 %0, %1, %2, %3;" : "=l"(d) : "l"(a), "l"(b), "l"(c));
    return d;
}
__device__ __forceinline__ unsigned long long pack2(float lo, float hi)
{
    unsigned long long d;
    asm("mov.b64 %0, {%1, %2};" : "=l"(d) : "f"(lo), "f"(hi));
    return d;
}
__device__ __forceinline__ void unpack2(unsigned long long v, float& lo, float& hi)
{
    asm("mov.b64 {%0, %1}, %2;" : "=f"(lo), "=f"(hi) : "l"(v));
}

// ---------------------------------------------------------------------------
// Scratch: single device global (no allocations allowed). ~173 MB.
__device__ __align__(16) float g_scratch[43200000];

// ---------------------------------------------------------------------------
// 1) TargetRegionDecoupler
__global__ void __launch_bounds__(256) k_decouple(
    const float* __restrict__ F, const float* __restrict__ dw,
    const float* __restrict__ db, float* __restrict__ F0, float* __restrict__ F1)
{
    int p = blockIdx.x * 256 + threadIdx.x;
    if (p >= NPIX) return;
    int b = p / HWHW, s = p - b * HWHW;
    const float* base = F + (size_t)b * CC * HWHW + s;
    float l0 = db[0], l1 = db[1];
#pragma unroll 4
    for (int c = 0; c < CC; ++c) {
        float v = base[c * HWHW];
        l0 += v * dw[c];
        l1 += v * dw[CC + c];
    }
    float m0 = 1.0f / (1.0f + expf(l1 - l0));
    float m1 = 1.0f - m0;
    float* o0 = F0 + (size_t)b * CC * HWHW + s;
    float* o1 = F1 + (size_t)b * CC * HWHW + s;
#pragma unroll 4
    for (int c = 0; c < CC; ++c) {
        float v = base[c * HWHW];
        o0[c * HWHW] = v * (1.0f + m0);
        o1[c * HWHW] = v * (1.0f + m1);
    }
}

// ---------------------------------------------------------------------------
// fused weight transposes:  w[OC][K] -> wT[K][64]  (zero-pad oc to 64)
__global__ void k_wtrans_all(
    const float* __restrict__ o1w, const float* __restrict__ o2w,
    const float* __restrict__ pww,
    float* __restrict__ wT1, float* __restrict__ wT2, float* __restrict__ wTp)
{
    int idx = blockIdx.x * 256 + threadIdx.x;
    if (idx < 2 * 2304 * 64) {
        int r = idx / (2304 * 64); int e = idx - r * 2304 * 64;
        int k = e / 64, oc = e - k * 64;
        wT1[idx] = (oc < 64) ? o1w[(size_t)r * 64 * 2304 + oc * 2304 + k] : 0.0f;
        return;
    }
    idx -= 2 * 2304 * 64;
    if (idx < 2 * 576 * 64) {
        int r = idx / (576 * 64); int e = idx - r * 576 * 64;
        int k = e / 64, oc = e - k * 64;
        wT2[r * 576 * 64 + e] = (oc < 18) ? o2w[(size_t)r * 18 * 576 + oc * 576 + k] : 0.0f;
        return;
    }
    idx -= 2 * 576 * 64;
    if (idx < 512 * 256) {
        int k = idx / 256, oc = idx - k * 256;
        wTp[idx] = pww[oc * 512 + k];
    }
}

// ---------------------------------------------------------------------------
// 2) 3x3 conv as implicit GEMM, pad=1.  OCT oc x 128 px tile, 256 threads.
//    Microtile: 4 oc (2 f32x2 pairs) x PXW px per thread.
//    OCT/4 * (128/PXW) must equal 256.
template<int IC, int OC, int OCT, int PXW, bool RELU>
__global__ void __launch_bounds__(256) k_conv3(
    const float* __restrict__ in0, const float* __restrict__ in1,
    const float* __restrict__ wTb, const float* __restrict__ biasb,
    float* __restrict__ out0, float* __restrict__ out1)
{
    const int K = IC * 9;
    constexpr int PXG = 128 / PXW;                 // thread groups along px
    static_assert((OCT / 4) * PXG == 256, "tile/thread mismatch");
    int r = blockIdx.y;
    const float* in   = r ? in1 : in0;
    const float* wT   = wTb + (size_t)r * K * 64;  // wT leading dim always 64
    const float* bias = biasb + r * OC;
    float* out = r ? out1 : out0;

    __shared__ __align__(16) float As[8][OCT];
    __shared__ __align__(16) float Bs[8][132];

    int tid = threadIdx.x;
    int tcn = tid % PXG;      // px group -> px = tcn*PXW + j
    int tr  = tid / PXG;      // oc group -> oc = tr*4 + {0..3}
    int px0 = blockIdx.x * 128;
    int loadpx = tid & 127;   // B-load: 2 threads per pixel, split taps
    int jh = tid >> 7;        // 0: taps 0-3, 1: taps 4-7
    int mypx = px0 + loadpx;
    int mb = mypx / HWHW, ms = mypx - mb * HWHW;
    int my = ms / WW, mx = ms - my * WW;
    const float* inb = in + (size_t)mb * IC * HWHW;

    unsigned long long acc2[2][PXW];
#pragma unroll
    for (int i = 0; i < 2; ++i)
#pragma unroll
        for (int j = 0; j < PXW; ++j) acc2[i][j] = 0ULL;

    for (int k0 = 0; k0 < K; k0 += 8) {
        // B (im2col on the fly): this thread fills 4 of the 8 tap rows
#pragma unroll
        for (int jj = 0; jj < 4; ++jj) {
            int k = k0 + jh * 4 + jj;
            int ic = k / 9, tap = k - ic * 9;
            int ky = tap / 3, kx = tap - ky * 3;
            int yy = my + ky - 1, xx = mx + kx - 1;
            float v = 0.0f;
            if ((unsigned)yy < (unsigned)HH && (unsigned)xx < (unsigned)WW)
                v = __ldg(&inb[ic * HWHW + yy * WW + xx]);
            Bs[jh * 4 + jj][loadpx] = v;
        }
        // A: 8 x OCT elements, OCT/32 per thread
#pragma unroll
        for (int j = 0; j < OCT / 32; ++j) {
            int e = tid + j * 256;
            int row = e / OCT, oc = e % OCT;
            As[row][oc] = wT[(k0 + row) * 64 + oc];
        }
        __syncthreads();
#pragma unroll
        for (int kk = 0; kk < 8; ++kk) {
            ulonglong2 ua = *(const ulonglong2*)&As[kk][tr * 4];
            unsigned long long A2[2] = { ua.x, ua.y };
            float bv[PXW];
#pragma unroll
            for (int q = 0; q < PXW / 4; ++q) {
                float4 b4 = *(const float4*)&Bs[kk][tcn * PXW + q * 4];
                bv[q * 4 + 0] = b4.x; bv[q * 4 + 1] = b4.y;
                bv[q * 4 + 2] = b4.z; bv[q * 4 + 3] = b4.w;
            }
#pragma unroll
            for (int j = 0; j < PXW; ++j) {
                unsigned long long bb = pack2(bv[j], bv[j]);
                acc2[0][j] = fma_f32x2(A2[0], bb, acc2[0][j]);
                acc2[1][j] = fma_f32x2(A2[1], bb, acc2[1][j]);
            }
        }
        __syncthreads();
    }

#pragma unroll
    for (int i2 = 0; i2 < 2; ++i2) {
        int oc0 = tr * 4 + i2 * 2, oc1 = oc0 + 1;
        float bv0 = (oc0 < OC) ? bias[oc0] : 0.0f;
        float bv1 = (oc1 < OC) ? bias[oc1] : 0.0f;
#pragma unroll
        for (int j = 0; j < PXW; ++j) {
            float lo, hi; unpack2(acc2[i2][j], lo, hi);
            int px = px0 + tcn * PXW + j;
            int b2 = px / HWHW, s2 = px - b2 * HWHW;
            if (oc0 < OC) {
                float v = lo + bv0; if (RELU) v = fmaxf(v, 0.0f);
                out[((size_t)b2 * OC + oc0) * HWHW + s2] = v;
            }
            if (oc1 < OC) {
                float v = hi + bv1; if (RELU) v = fmaxf(v, 0.0f);
                out[((size_t)b2 * OC + oc1) * HWHW + s2] = v;
            }
        }
    }
}

// ---------------------------------------------------------------------------
// 3) NCHW -> NHWC transpose (per region via blockIdx.z = r*8 + b)
__global__ void k_tr(const float* __restrict__ s0, const float* __restrict__ s1,
                     float* __restrict__ d0, float* __restrict__ d1)
{
    __shared__ float tile[32][33];
    int z = blockIdx.z; int r = z >> 3, b = z & 7;
    const float* src = (r ? s1 : s0) + (size_t)b * CC * HWHW;
    float* dst = (r ? d1 : d0) + (size_t)b * HWHW * CC;
    int c0 = blockIdx.y * 32, sp0 = blockIdx.x * 32;
    int tx = threadIdx.x, ty = threadIdx.y;
#pragma unroll
    for (int i = ty; i < 32; i += 8)
        tile[i][tx] = src[(c0 + i) * HWHW + sp0 + tx];
    __syncthreads();
#pragma unroll
    for (int i = ty; i < 32; i += 8)
        dst[(size_t)(sp0 + i) * CC + c0 + tx] = tile[tx][i];
}

// ---------------------------------------------------------------------------
// 4) AKG part 1
__global__ void __launch_bounds__(64) k_akgpool(
    const float* __restrict__ F0, const float* __restrict__ F1,
    const float* __restrict__ dwwb, float* __restrict__ dvec)
{
    int gb = blockIdx.x; int r = gb >> 11; int bc = gb & 2047;
    int c = bc & 255;
    const float* P = (r ? F1 : F0) + (size_t)bc * HWHW;
    const float* dww = dwwb + r * CC * 9 + c * 9;
    __shared__ float pool[49];
    __shared__ float cnv[49];
    int t = threadIdx.x;
    if (t < 49) {
        int bi = t / 7, bj = t - bi * 7;
        const float* q = P + bi * 8 * WW + bj * 8;
        float sm = 0.0f;
#pragma unroll
        for (int u = 0; u < 8; ++u)
#pragma unroll
            for (int v = 0; v < 8; ++v) sm += q[u * WW + v];
        pool[t] = sm * 0.015625f;
    }
    __syncthreads();
    if (t < 49) {
        int pi = t / 7, pj = t - pi * 7;
        float sm = 0.0f;
#pragma unroll
        for (int u = 0; u < 3; ++u)
#pragma unroll
            for (int v = 0; v < 3; ++v) {
                int yy = pi + u - 1, xx = pj + v - 1;
                if ((unsigned)yy < 7u && (unsigned)xx < 7u)
                    sm += dww[u * 3 + v] * pool[yy * 7 + xx];
            }
        cnv[t] = fmaxf(sm, 0.0f);
    }
    __syncthreads();
    if (t == 0) {
        float sm = 0.0f;
        for (int i = 0; i < 49; ++i) sm += cnv[i];
        dvec[r * 2048 + bc] = sm * (1.0f / 49.0f);
    }
}

// 5) AKG part 2: 1x1 head (2304x256) + tanh
__global__ void __launch_bounds__(256) k_akghead(
    const float* __restrict__ dvec, const float* __restrict__ hwb,
    const float* __restrict__ hbb, float* __restrict__ Kout)
{
    int b = blockIdx.x, r = blockIdx.y;
    const float* hw = hwb + (size_t)r * 2304 * 256;
    const float* hb = hbb + r * 2304;
    __shared__ float dv[256];
    dv[threadIdx.x] = dvec[r * 2048 + b * 256 + threadIdx.x];
    __syncthreads();
    for (int oc = threadIdx.x; oc < 2304; oc += 256) {
        const float* w = hw + (size_t)oc * 256;
        float sm = hb[oc];
#pragma unroll 8
        for (int c2 = 0; c2 < 256; ++c2) sm += w[c2] * dv[c2];
        Kout[(r * 8 + b) * 2304 + oc] = tanhf(sm);
    }
}

// ---------------------------------------------------------------------------
// 6) dynamic depthwise deformable conv (NHWC gather).
__global__ void __launch_bounds__(256) k_deform(
    const float* __restrict__ F0n, const float* __restrict__ F1n,
    const float* __restrict__ p0, const float* __restrict__ p1,
    const float* __restrict__ Kall, float* __restrict__ D0, float* __restrict__ D1)
{
    int y = blockIdx.x, b = blockIdx.y, r = blockIdx.z;
    const float* Fn = (r ? F1n : F0n) + (size_t)b * HWHW * CC;
    const float* off = (r ? p1 : p0) + (size_t)b * 18 * HWHW;
    const float* Kw = Kall + (r * 8 + b) * 2304;
    float* Dn = (r ? D1 : D0) + (size_t)b * HWHW * CC;

    __shared__ int   sIdx[9][56][4];
    __shared__ float sW[9][56][4];
    __shared__ float sK[9][256];
    int tid = threadIdx.x;
    for (int i = tid; i < 2304; i += 256) {
        int c = i / 9, t = i - c * 9;
        sK[t][c] = Kw[i];
    }
    for (int i = tid; i < 504; i += 256) {
        int t = i / 56, x = i - t * 56;
        int ky = t / 3, kx = t - ky * 3;
        float dy = off[(2 * t) * HWHW + y * WW + x];
        float dx = off[(2 * t + 1) * HWHW + y * WW + x];
        float py = (float)(y + ky - 1) + dy;
        float px = (float)(x + kx - 1) + dx;
        float fy = floorf(py), fx = floorf(px);
        float wy1 = py - fy, wx1 = px - fx;
        float wy0 = 1.0f - wy1, wx0 = 1.0f - wx1;
        int y0 = (int)fy, x0 = (int)fx;
        int y1 = y0 + 1, x1 = x0 + 1;
        bool vy0 = (y0 >= 0) && (y0 < HH);
        bool vy1 = (y1 >= 0) && (y1 < HH);
        bool vx0 = (x0 >= 0) && (x0 < WW);
        bool vx1 = (x1 >= 0) && (x1 < WW);
        int cy0 = min(max(y0, 0), HH - 1), cy1 = min(max(y1, 0), HH - 1);
        int cx0 = min(max(x0, 0), WW - 1), cx1 = min(max(x1, 0), WW - 1);
        sIdx[t][x][0] = (cy0 * WW + cx0) * CC; sW[t][x][0] = (vy0 && vx0) ? wy0 * wx0 : 0.0f;
        sIdx[t][x][1] = (cy0 * WW + cx1) * CC; sW[t][x][1] = (vy0 && vx1) ? wy0 * wx1 : 0.0f;
        sIdx[t][x][2] = (cy1 * WW + cx0) * CC; sW[t][x][2] = (vy1 && vx0) ? wy1 * wx0 : 0.0f;
        sIdx[t][x][3] = (cy1 * WW + cx1) * CC; sW[t][x][3] = (vy1 && vx1) ? wy1 * wx1 : 0.0f;
    }
    __syncthreads();
    int lane = tid & 31, wrp = tid >> 5;   // 8 warps; warp owns x stripe
    for (int x = wrp; x < 56; x += 8) {
        float acc[8];
#pragma unroll
        for (int q = 0; q < 8; ++q) acc[q] = 0.0f;
#pragma unroll
        for (int t = 0; t < 9; ++t) {
            int i0 = sIdx[t][x][0], i1 = sIdx[t][x][1];
            int i2 = sIdx[t][x][2], i3 = sIdx[t][x][3];
            float w0 = sW[t][x][0], w1 = sW[t][x][1];
            float w2 = sW[t][x][2], w3 = sW[t][x][3];
#pragma unroll
            for (int q = 0; q < 8; ++q) {
                int c = q * 32 + lane;
                float v = w0 * Fn[i0 + c] + w1 * Fn[i1 + c]
                        + w2 * Fn[i2 + c] + w3 * Fn[i3 + c];
                acc[q] += sK[t][c] * v;
            }
        }
        float* o = Dn + ((size_t)y * WW + x) * CC;
#pragma unroll
        for (int q = 0; q < 8; ++q) o[q * 32 + lane] = acc[q];
    }
}

// ---------------------------------------------------------------------------
// 7) pw2 1x1 conv over concat(D0,D1) (K=512), NHWC input, NCHW output.
__global__ void __launch_bounds__(128) k_pw2(
    const float* __restrict__ D0, const float* __restrict__ D1,
    const float* __restrict__ wT, const float* __restrict__ bias,
    float* __restrict__ out)
{
    __shared__ __align__(16) float As[8][64];
    __shared__ __align__(16) float Bs[8][132];
    int tid = threadIdx.x;
    int tr = tid >> 4, tcn = tid & 15;
    int px0 = blockIdx.x * 128;
    int ocb = blockIdx.y * 64;
    int mypx = px0 + tid;

    unsigned long long acc2[4][8];
#pragma unroll
    for (int i = 0; i < 4; ++i)
#pragma unroll
        for (int j = 0; j < 8; ++j) acc2[i][j] = 0ULL;

    for (int k0 = 0; k0 < 512; k0 += 8) {
        const float* src = (k0 < 256) ? (D0 + (size_t)mypx * 256 + k0)
                                      : (D1 + (size_t)mypx * 256 + (k0 - 256));
        float4 v0 = *(const float4*)src;
        float4 v1 = *(const float4*)(src + 4);
        Bs[0][tid] = v0.x; Bs[1][tid] = v0.y; Bs[2][tid] = v0.z; Bs[3][tid] = v0.w;
        Bs[4][tid] = v1.x; Bs[5][tid] = v1.y; Bs[6][tid] = v1.z; Bs[7][tid] = v1.w;
#pragma unroll
        for (int j = 0; j < 4; ++j) {
            int rrow = (tid >> 6) + j * 2;
            int oc = tid & 63;
            As[rrow][oc] = wT[(k0 + rrow) * 256 + ocb + oc];
        }
        __syncthreads();
#pragma unroll
        for (int kk = 0; kk < 8; ++kk) {
            ulonglong2 ua0 = *(const ulonglong2*)&As[kk][tr * 8];
            ulonglong2 ua1 = *(const ulonglong2*)&As[kk][tr * 8 + 4];
            unsigned long long A2[4] = { ua0.x, ua0.y, ua1.x, ua1.y };
            float4 b0 = *(const float4*)&Bs[kk][tcn * 8];
            float4 b1 = *(const float4*)&Bs[kk][tcn * 8 + 4];
            float bv[8] = { b0.x, b0.y, b0.z, b0.w, b1.x, b1.y, b1.z, b1.w };
#pragma unroll
            for (int j = 0; j < 8; ++j) {
                unsigned long long bb = pack2(bv[j], bv[j]);
#pragma unroll
                for (int i2 = 0; i2 < 4; ++i2)
                    acc2[i2][j] = fma_f32x2(A2[i2], bb, acc2[i2][j]);
            }
        }
        __syncthreads();
    }

#pragma unroll
    for (int i2 = 0; i2 < 4; ++i2) {
        int oc0 = ocb + tr * 8 + i2 * 2, oc1 = oc0 + 1;
        float bv0 = bias[oc0], bv1 = bias[oc1];
#pragma unroll
        for (int j = 0; j < 8; ++j) {
            float lo, hi; unpack2(acc2[i2][j], lo, hi);
            int px = px0 + tcn * 8 + j;
            int b2 = px / HWHW, s2 = px - b2 * HWHW;
            out[((size_t)b2 * CC + oc0) * HWHW + s2] = lo + bv0;
            out[((size_t)b2 * CC + oc1) * HWHW + s2] = hi + bv1;
        }
    }
}

// ---------------------------------------------------------------------------
// 8) BatchNorm (training-mode batch stats), two deterministic passes
__global__ void __launch_bounds__(256) k_bnred(
    const float* __restrict__ O, const float* __restrict__ gamma,
    const float* __restrict__ beta, float* __restrict__ stat)
{
    int c = blockIdx.x;
    float s = 0.0f, q = 0.0f;
    for (int i = threadIdx.x; i < NPIX; i += 256) {
        int b = i / HWHW, sp = i - b * HWHW;
        float v = O[((size_t)b * CC + c) * HWHW + sp];
        s += v; q += v * v;
    }
    __shared__ float ss[256], qq[256];
    ss[threadIdx.x] = s; qq[threadIdx.x] = q;
    __syncthreads();
    for (int st = 128; st > 0; st >>= 1) {
        if (threadIdx.x < st) {
            ss[threadIdx.x] += ss[threadIdx.x + st];
            qq[threadIdx.x] += qq[threadIdx.x + st];
        }
        __syncthreads();
    }
    if (threadIdx.x == 0) {
        float mean = ss[0] * (1.0f / (float)NPIX);
        float var  = qq[0] * (1.0f / (float)NPIX) - mean * mean;
        float sc = gamma[c] * rsqrtf(var + 1e-5f);
        stat[c] = sc;
        stat[256 + c] = beta[c] - mean * sc;
    }
}

__global__ void k_bnapp(float* __restrict__ O, const float* __restrict__ stat)
{
    int idx = (blockIdx.x * 256 + threadIdx.x) * 2;   // grid covers NF exactly
    float2 v = *(float2*)&O[idx];
    int c = (idx / HWHW) & 255;
    float scl = stat[c], sh = stat[256 + c];
    v.x = v.x * scl + sh;
    v.y = v.y * scl + sh;
    *(float2*)&O[idx] = v;
}

// ---------------------------------------------------------------------------
extern "C" void kernel_launch(void* const* d_in, const int* in_sizes, int n_in,
                              void* d_out, int out_size)
{
    const float* F_c    = (const float*)d_in[0];
    const float* dec_w  = (const float*)d_in[1];
    const float* dec_b  = (const float*)d_in[2];
    const float* off1_w = (const float*)d_in[3];
    const float* off1_b = (const float*)d_in[4];
    const float* off2_w = (const float*)d_in[5];
    const float* off2_b = (const float*)d_in[6];
    const float* akgdw  = (const float*)d_in[7];
    const float* hw     = (const float*)d_in[8];
    const float* hb     = (const float*)d_in[9];
    const float* pw2_w  = (const float*)d_in[10];
    const float* pw2_b  = (const float*)d_in[11];
    const float* gamma  = (const float*)d_in[12];
    const float* beta   = (const float*)d_in[13];
    float* out = (float*)d_out;

    float* sc = nullptr;
    cudaGetSymbolAddress((void**)&sc, g_scratch);

    float* F0   = sc;
    float* F1   = sc + (size_t)NF;
    float* F0n  = sc + (size_t)2 * NF;
    float* F1n  = sc + (size_t)3 * NF;
    float* D0   = sc + (size_t)4 * NF;
    float* D1   = sc + (size_t)5 * NF;
    float* h    = sc + (size_t)6 * NF;        // 2 * 1605632
    float* pp   = h + 3211264;                 // 2 * 451584
    float* wT1  = pp + 903168;                 // 2 * 147456
    float* wT2  = wT1 + 294912;                // 2 * 36864
    float* wTp  = wT2 + 73728;                 // 131072
    float* dvec = wTp + 131072;                // 4096
    float* Kb   = dvec + 4096;                 // 36864
    float* stat = Kb + 36864;                  // 512

    // 1) decouple
    k_decouple<<<98, 256>>>(F_c, dec_w, dec_b, F0, F1);

    // fused weight transposes
    int wtot = 2 * 2304 * 64 + 2 * 576 * 64 + 512 * 256;
    k_wtrans_all<<<(wtot + 255) / 256, 256>>>(off1_w, off2_w, pw2_w, wT1, wT2, wTp);

    // 2) offset generator convs (both regions per launch), 256 threads/block
    dim3 g1(196, 2);
    k_conv3<256, 64, 64, 8, true ><<<g1, 256>>>(F0, F1, wT1, off1_b, h, h + 1605632);
    k_conv3< 64, 18, 32, 4, false><<<g1, 256>>>(h, h + 1605632, wT2, off2_b, pp, pp + 451584);

    // 3) NHWC copies for gather
    k_tr<<<dim3(98, 8, 16), dim3(32, 8)>>>(F0, F1, F0n, F1n);

    // 4/5) AKG
    k_akgpool<<<4096, 64>>>(F0, F1, akgdw, dvec);
    k_akghead<<<dim3(8, 2), 256>>>(dvec, hw, hb, Kb);

    // 6) deformable dynamic depthwise
    k_deform<<<dim3(56, 8, 2), 256>>>(F0n, F1n, pp, pp + 451584, Kb, D0, D1);

    // 7) pointwise merge -> pre-BN output
    k_pw2<<<dim3(196, 4), 128>>>(D0, D1, wTp, pw2_b, out);

    // 8) BN (training-mode batch stats)
    k_bnred<<<256, 256>>>(out, gamma, beta, stat);
    k_bnapp<<<12544, 256>>>(out, stat);
}

// round 6
// speedup vs baseline: 1.1291x; 1.1291x over previous
#include <cuda_runtime.h>
#include <cuda_bf16.h>
#include <math.h>

// Problem constants (fixed shapes)
#define BB 8
#define CC 256
#define HH 56
#define WW 56
#define HWHW 3136            // 56*56
#define NPIX 25088           // B*H*W
#define NF 6422528           // B*C*H*W
#define RR 2
#define HID 64

// ---------------------------------------------------------------------------
// packed f32x2 helpers
__device__ __forceinline__ unsigned long long fma_f32x2(
    unsigned long long a, unsigned long long b, unsigned long long c)
{
    unsigned long long d;
    asm("fma.rn.f32x2 %0, %1, %2, %3;" : "=l"(d) : "l"(a), "l"(b), "l"(c));
    return d;
}
__device__ __forceinline__ unsigned long long pack2(float lo, float hi)
{
    unsigned long long d;
    asm("mov.b64 %0, {%1, %2};" : "=l"(d) : "f"(lo), "f"(hi));
    return d;
}
__device__ __forceinline__ void unpack2(unsigned long long v, float& lo, float& hi)
{
    asm("mov.b64 {%0, %1}, %2;" : "=f"(lo), "=f"(hi) : "l"(v));
}

// ---------------------------------------------------------------------------
// Scratch: single device global (no allocations allowed). ~173 MB.
__device__ __align__(16) float g_scratch[43200000];

// ---------------------------------------------------------------------------
// 1) TargetRegionDecoupler — now also emits NHWC copies (replaces k_tr).
__global__ void __launch_bounds__(256) k_decouple(
    const float* __restrict__ F, const float* __restrict__ dw,
    const float* __restrict__ db, float* __restrict__ F0, float* __restrict__ F1,
    float* __restrict__ F0n, float* __restrict__ F1n)
{
    int p = blockIdx.x * 256 + threadIdx.x;
    if (p >= NPIX) return;
    int b = p / HWHW, s = p - b * HWHW;
    const float* base = F + (size_t)b * CC * HWHW + s;
    float l0 = db[0], l1 = db[1];
#pragma unroll 4
    for (int c = 0; c < CC; ++c) {
        float v = base[c * HWHW];
        l0 += v * dw[c];
        l1 += v * dw[CC + c];
    }
    float m0 = 1.0f / (1.0f + expf(l1 - l0));
    float m1 = 1.0f - m0;
    float* o0 = F0 + (size_t)b * CC * HWHW + s;
    float* o1 = F1 + (size_t)b * CC * HWHW + s;
    float* o0n = F0n + ((size_t)b * HWHW + s) * CC;
    float* o1n = F1n + ((size_t)b * HWHW + s) * CC;
    for (int c = 0; c < CC; c += 4) {
        float4 w0, w1;
        float v;
        v = base[(c + 0) * HWHW]; w0.x = v * (1.0f + m0); w1.x = v * (1.0f + m1);
        v = base[(c + 1) * HWHW]; w0.y = v * (1.0f + m0); w1.y = v * (1.0f + m1);
        v = base[(c + 2) * HWHW]; w0.z = v * (1.0f + m0); w1.z = v * (1.0f + m1);
        v = base[(c + 3) * HWHW]; w0.w = v * (1.0f + m0); w1.w = v * (1.0f + m1);
        o0[(c + 0) * HWHW] = w0.x; o0[(c + 1) * HWHW] = w0.y;
        o0[(c + 2) * HWHW] = w0.z; o0[(c + 3) * HWHW] = w0.w;
        o1[(c + 0) * HWHW] = w1.x; o1[(c + 1) * HWHW] = w1.y;
        o1[(c + 2) * HWHW] = w1.z; o1[(c + 3) * HWHW] = w1.w;
        *(float4*)&o0n[c] = w0;
        *(float4*)&o1n[c] = w1;
    }
}

// ---------------------------------------------------------------------------
// fused weight transposes:  w[OC][K] -> wT[K][64]  (zero-pad oc to 64)
__global__ void k_wtrans_all(
    const float* __restrict__ o1w, const float* __restrict__ o2w,
    const float* __restrict__ pww,
    float* __restrict__ wT1, float* __restrict__ wT2, float* __restrict__ wTp)
{
    int idx = blockIdx.x * 256 + threadIdx.x;
    if (idx < 2 * 2304 * 64) {
        int r = idx / (2304 * 64); int e = idx - r * 2304 * 64;
        int k = e / 64, oc = e - k * 64;
        wT1[idx] = (oc < 64) ? o1w[(size_t)r * 64 * 2304 + oc * 2304 + k] : 0.0f;
        return;
    }
    idx -= 2 * 2304 * 64;
    if (idx < 2 * 576 * 64) {
        int r = idx / (576 * 64); int e = idx - r * 576 * 64;
        int k = e / 64, oc = e - k * 64;
        wT2[r * 576 * 64 + e] = (oc < 18) ? o2w[(size_t)r * 18 * 576 + oc * 576 + k] : 0.0f;
        return;
    }
    idx -= 2 * 576 * 64;
    if (idx < 512 * 256) {
        int k = idx / 256, oc = idx - k * 256;
        wTp[idx] = pww[oc * 512 + k];
    }
}

// ---------------------------------------------------------------------------
// B-fragment loader (im2col on the fly) for 3x3 conv, pad=1
template<int IC>
__device__ __forceinline__ void conv_loadB(
    const float* __restrict__ inb, int my, int mx, int k0, float b[8])
{
#pragma unroll
    for (int j = 0; j < 8; ++j) {
        int k = k0 + j;
        int ic = k / 9, tap = k - ic * 9;
        int ky = tap / 3, kx = tap - ky * 3;
        int yy = my + ky - 1, xx = mx + kx - 1;
        float v = 0.0f;
        if ((unsigned)yy < (unsigned)HH && (unsigned)xx < (unsigned)WW)
            v = __ldg(&inb[ic * HWHW + yy * WW + xx]);
        b[j] = v;
    }
}

// ---------------------------------------------------------------------------
// 2a) conv1: 3x3 conv as implicit GEMM, 64oc x 128px tile, 128 threads,
//     8oc x 8px microtile (R4 tiling) + global->register prefetch.
template<int IC, int OC, bool RELU>
__global__ void __launch_bounds__(128) k_conv3a(
    const float* __restrict__ in0, const float* __restrict__ in1,
    const float* __restrict__ wTb, const float* __restrict__ biasb,
    float* __restrict__ out0, float* __restrict__ out1)
{
    const int K = IC * 9;
    const int NT = K / 8;
    int r = blockIdx.y;
    const float* in   = r ? in1 : in0;
    const float* wT   = wTb + (size_t)r * K * 64;
    const float* bias = biasb + r * OC;
    float* out = r ? out1 : out0;

    __shared__ __align__(16) float As[8][64];
    __shared__ __align__(16) float Bs[8][132];
    int tid = threadIdx.x;
    int tr = tid >> 4, tcn = tid & 15;
    int px0 = blockIdx.x * 128;
    int mypx = px0 + tid;
    int mb = mypx / HWHW; int ms = mypx - mb * HWHW;
    int my = ms / WW, mx = ms - my * WW;
    const float* inb = in + (size_t)mb * IC * HWHW;

    unsigned long long acc2[4][8];
#pragma unroll
    for (int i = 0; i < 4; ++i)
#pragma unroll
        for (int j = 0; j < 8; ++j) acc2[i][j] = 0ULL;

    float bReg[8], aReg[4], bRegN[8], aRegN[4];
    conv_loadB<IC>(inb, my, mx, 0, bReg);
#pragma unroll
    for (int j = 0; j < 4; ++j)
        aReg[j] = wT[((tid >> 6) + j * 2) * 64 + (tid & 63)];

    for (int t = 0; t < NT; ++t) {
#pragma unroll
        for (int j = 0; j < 8; ++j) Bs[j][tid] = bReg[j];
#pragma unroll
        for (int j = 0; j < 4; ++j) As[(tid >> 6) + j * 2][tid & 63] = aReg[j];
        __syncthreads();
        if (t + 1 < NT) {
            // prefetch next tile into registers — overlaps with compute below
            conv_loadB<IC>(inb, my, mx, (t + 1) * 8, bRegN);
#pragma unroll
            for (int j = 0; j < 4; ++j)
                aRegN[j] = wT[((t + 1) * 8 + (tid >> 6) + j * 2) * 64 + (tid & 63)];
        }
#pragma unroll
        for (int kk = 0; kk < 8; ++kk) {
            ulonglong2 ua0 = *(const ulonglong2*)&As[kk][tr * 8];
            ulonglong2 ua1 = *(const ulonglong2*)&As[kk][tr * 8 + 4];
            unsigned long long A2[4] = { ua0.x, ua0.y, ua1.x, ua1.y };
            float4 b0 = *(const float4*)&Bs[kk][tcn * 8];
            float4 b1 = *(const float4*)&Bs[kk][tcn * 8 + 4];
            float bv[8] = { b0.x, b0.y, b0.z, b0.w, b1.x, b1.y, b1.z, b1.w };
#pragma unroll
            for (int j = 0; j < 8; ++j) {
                unsigned long long bb = pack2(bv[j], bv[j]);
#pragma unroll
                for (int i2 = 0; i2 < 4; ++i2)
                    acc2[i2][j] = fma_f32x2(A2[i2], bb, acc2[i2][j]);
            }
        }
        __syncthreads();
#pragma unroll
        for (int j = 0; j < 8; ++j) bReg[j] = bRegN[j];
#pragma unroll
        for (int j = 0; j < 4; ++j) aReg[j] = aRegN[j];
    }

#pragma unroll
    for (int i2 = 0; i2 < 4; ++i2) {
        int oc0 = tr * 8 + i2 * 2, oc1 = oc0 + 1;
        float bv0 = (oc0 < OC) ? bias[oc0] : 0.0f;
        float bv1 = (oc1 < OC) ? bias[oc1] : 0.0f;
#pragma unroll
        for (int j = 0; j < 8; ++j) {
            float lo, hi; unpack2(acc2[i2][j], lo, hi);
            int px = px0 + tcn * 8 + j;
            int b2 = px / HWHW, s2 = px - b2 * HWHW;
            if (oc0 < OC) {
                float v = lo + bv0; if (RELU) v = fmaxf(v, 0.0f);
                out[((size_t)b2 * OC + oc0) * HWHW + s2] = v;
            }
            if (oc1 < OC) {
                float v = hi + bv1; if (RELU) v = fmaxf(v, 0.0f);
                out[((size_t)b2 * OC + oc1) * HWHW + s2] = v;
            }
        }
    }
}

// ---------------------------------------------------------------------------
// 2b) conv2: OCT oc x 128 px tile, 256 threads, 4oc x PXW px microtile
//     (R5 tiling, measured 85us) + prefetch.
template<int IC, int OC, int OCT, int PXW, bool RELU>
__global__ void __launch_bounds__(256) k_conv3b(
    const float* __restrict__ in0, const float* __restrict__ in1,
    const float* __restrict__ wTb, const float* __restrict__ biasb,
    float* __restrict__ out0, float* __restrict__ out1)
{
    const int K = IC * 9;
    const int NT = K / 8;
    constexpr int PXG = 128 / PXW;
    static_assert((OCT / 4) * PXG == 256, "tile/thread mismatch");
    int r = blockIdx.y;
    const float* in   = r ? in1 : in0;
    const float* wT   = wTb + (size_t)r * K * 64;
    const float* bias = biasb + r * OC;
    float* out = r ? out1 : out0;

    __shared__ __align__(16) float As[8][OCT];
    __shared__ __align__(16) float Bs[8][132];

    int tid = threadIdx.x;
    int tcn = tid % PXG;
    int tr  = tid / PXG;
    int px0 = blockIdx.x * 128;
    int loadpx = tid & 127;
    int jh = tid >> 7;
    int mypx = px0 + loadpx;
    int mb = mypx / HWHW, ms = mypx - mb * HWHW;
    int my = ms / WW, mx = ms - my * WW;
    const float* inb = in + (size_t)mb * IC * HWHW;

    unsigned long long acc2[2][PXW];
#pragma unroll
    for (int i = 0; i < 2; ++i)
#pragma unroll
        for (int j = 0; j < PXW; ++j) acc2[i][j] = 0ULL;

    float bReg[4], aReg[OCT / 32], bRegN[4], aRegN[OCT / 32];
    // prologue loads: this thread owns taps [jh*4, jh*4+4) of pixel loadpx
    {
#pragma unroll
        for (int jj = 0; jj < 4; ++jj) {
            int k = jh * 4 + jj;
            int ic = k / 9, tap = k - ic * 9;
            int ky = tap / 3, kx = tap - ky * 3;
            int yy = my + ky - 1, xx = mx + kx - 1;
            float v = 0.0f;
            if ((unsigned)yy < (unsigned)HH && (unsigned)xx < (unsigned)WW)
                v = __ldg(&inb[ic * HWHW + yy * WW + xx]);
            bReg[jj] = v;
        }
#pragma unroll
        for (int j = 0; j < OCT / 32; ++j) {
            int e = tid + j * 256;
            int row = e / OCT, oc = e % OCT;
            aReg[j] = wT[row * 64 + oc];
        }
    }

    for (int t = 0; t < NT; ++t) {
#pragma unroll
        for (int jj = 0; jj < 4; ++jj) Bs[jh * 4 + jj][loadpx] = bReg[jj];
#pragma unroll
        for (int j = 0; j < OCT / 32; ++j) {
            int e = tid + j * 256;
            int row = e / OCT, oc = e % OCT;
            As[row][oc] = aReg[j];
        }
        __syncthreads();
        if (t + 1 < NT) {
            int k0 = (t + 1) * 8;
#pragma unroll
            for (int jj = 0; jj < 4; ++jj) {
                int k = k0 + jh * 4 + jj;
                int ic = k / 9, tap = k - ic * 9;
                int ky = tap / 3, kx = tap - ky * 3;
                int yy = my + ky - 1, xx = mx + kx - 1;
                float v = 0.0f;
                if ((unsigned)yy < (unsigned)HH && (unsigned)xx < (unsigned)WW)
                    v = __ldg(&inb[ic * HWHW + yy * WW + xx]);
                bRegN[jj] = v;
            }
#pragma unroll
            for (int j = 0; j < OCT / 32; ++j) {
                int e = tid + j * 256;
                int row = e / OCT, oc = e % OCT;
                aRegN[j] = wT[(k0 + row) * 64 + oc];
            }
        }
#pragma unroll
        for (int kk = 0; kk < 8; ++kk) {
            ulonglong2 ua = *(const ulonglong2*)&As[kk][tr * 4];
            unsigned long long A2[2] = { ua.x, ua.y };
            float bv[PXW];
#pragma unroll
            for (int q = 0; q < PXW / 4; ++q) {
                float4 b4 = *(const float4*)&Bs[kk][tcn * PXW + q * 4];
                bv[q * 4 + 0] = b4.x; bv[q * 4 + 1] = b4.y;
                bv[q * 4 + 2] = b4.z; bv[q * 4 + 3] = b4.w;
            }
#pragma unroll
            for (int j = 0; j < PXW; ++j) {
                unsigned long long bb = pack2(bv[j], bv[j]);
                acc2[0][j] = fma_f32x2(A2[0], bb, acc2[0][j]);
                acc2[1][j] = fma_f32x2(A2[1], bb, acc2[1][j]);
            }
        }
        __syncthreads();
#pragma unroll
        for (int jj = 0; jj < 4; ++jj) bReg[jj] = bRegN[jj];
#pragma unroll
        for (int j = 0; j < OCT / 32; ++j) aReg[j] = aRegN[j];
    }

#pragma unroll
    for (int i2 = 0; i2 < 2; ++i2) {
        int oc0 = tr * 4 + i2 * 2, oc1 = oc0 + 1;
        float bv0 = (oc0 < OC) ? bias[oc0] : 0.0f;
        float bv1 = (oc1 < OC) ? bias[oc1] : 0.0f;
#pragma unroll
        for (int j = 0; j < PXW; ++j) {
            float lo, hi; unpack2(acc2[i2][j], lo, hi);
            int px = px0 + tcn * PXW + j;
            int b2 = px / HWHW, s2 = px - b2 * HWHW;
            if (oc0 < OC) {
                float v = lo + bv0; if (RELU) v = fmaxf(v, 0.0f);
                out[((size_t)b2 * OC + oc0) * HWHW + s2] = v;
            }
            if (oc1 < OC) {
                float v = hi + bv1; if (RELU) v = fmaxf(v, 0.0f);
                out[((size_t)b2 * OC + oc1) * HWHW + s2] = v;
            }
        }
    }
}

// ---------------------------------------------------------------------------
// 4) AKG part 1
__global__ void __launch_bounds__(64) k_akgpool(
    const float* __restrict__ F0, const float* __restrict__ F1,
    const float* __restrict__ dwwb, float* __restrict__ dvec)
{
    int gb = blockIdx.x; int r = gb >> 11; int bc = gb & 2047;
    int c = bc & 255;
    const float* P = (r ? F1 : F0) + (size_t)bc * HWHW;
    const float* dww = dwwb + r * CC * 9 + c * 9;
    __shared__ float pool[49];
    __shared__ float cnv[49];
    int t = threadIdx.x;
    if (t < 49) {
        int bi = t / 7, bj = t - bi * 7;
        const float* q = P + bi * 8 * WW + bj * 8;
        float sm = 0.0f;
#pragma unroll
        for (int u = 0; u < 8; ++u)
#pragma unroll
            for (int v = 0; v < 8; ++v) sm += q[u * WW + v];
        pool[t] = sm * 0.015625f;
    }
    __syncthreads();
    if (t < 49) {
        int pi = t / 7, pj = t - pi * 7;
        float sm = 0.0f;
#pragma unroll
        for (int u = 0; u < 3; ++u)
#pragma unroll
            for (int v = 0; v < 3; ++v) {
                int yy = pi + u - 1, xx = pj + v - 1;
                if ((unsigned)yy < 7u && (unsigned)xx < 7u)
                    sm += dww[u * 3 + v] * pool[yy * 7 + xx];
            }
        cnv[t] = fmaxf(sm, 0.0f);
    }
    __syncthreads();
    if (t == 0) {
        float sm = 0.0f;
        for (int i = 0; i < 49; ++i) sm += cnv[i];
        dvec[r * 2048 + bc] = sm * (1.0f / 49.0f);
    }
}

// 5) AKG part 2: 1x1 head (2304x256) + tanh
__global__ void __launch_bounds__(256) k_akghead(
    const float* __restrict__ dvec, const float* __restrict__ hwb,
    const float* __restrict__ hbb, float* __restrict__ Kout)
{
    int b = blockIdx.x, r = blockIdx.y;
    const float* hw = hwb + (size_t)r * 2304 * 256;
    const float* hb = hbb + r * 2304;
    __shared__ float dv[256];
    dv[threadIdx.x] = dvec[r * 2048 + b * 256 + threadIdx.x];
    __syncthreads();
    for (int oc = threadIdx.x; oc < 2304; oc += 256) {
        const float* w = hw + (size_t)oc * 256;
        float sm = hb[oc];
#pragma unroll 8
        for (int c2 = 0; c2 < 256; ++c2) sm += w[c2] * dv[c2];
        Kout[(r * 8 + b) * 2304 + oc] = tanhf(sm);
    }
}

// ---------------------------------------------------------------------------
// 6) dynamic depthwise deformable conv (NHWC gather).
__global__ void __launch_bounds__(256) k_deform(
    const float* __restrict__ F0n, const float* __restrict__ F1n,
    const float* __restrict__ p0, const float* __restrict__ p1,
    const float* __restrict__ Kall, float* __restrict__ D0, float* __restrict__ D1)
{
    int y = blockIdx.x, b = blockIdx.y, r = blockIdx.z;
    const float* Fn = (r ? F1n : F0n) + (size_t)b * HWHW * CC;
    const float* off = (r ? p1 : p0) + (size_t)b * 18 * HWHW;
    const float* Kw = Kall + (r * 8 + b) * 2304;
    float* Dn = (r ? D1 : D0) + (size_t)b * HWHW * CC;

    __shared__ int   sIdx[9][56][4];
    __shared__ float sW[9][56][4];
    __shared__ float sK[9][256];
    int tid = threadIdx.x;
    for (int i = tid; i < 2304; i += 256) {
        int c = i / 9, t = i - c * 9;
        sK[t][c] = Kw[i];
    }
    for (int i = tid; i < 504; i += 256) {
        int t = i / 56, x = i - t * 56;
        int ky = t / 3, kx = t - ky * 3;
        float dy = off[(2 * t) * HWHW + y * WW + x];
        float dx = off[(2 * t + 1) * HWHW + y * WW + x];
        float py = (float)(y + ky - 1) + dy;
        float px = (float)(x + kx - 1) + dx;
        float fy = floorf(py), fx = floorf(px);
        float wy1 = py - fy, wx1 = px - fx;
        float wy0 = 1.0f - wy1, wx0 = 1.0f - wx1;
        int y0 = (int)fy, x0 = (int)fx;
        int y1 = y0 + 1, x1 = x0 + 1;
        bool vy0 = (y0 >= 0) && (y0 < HH);
        bool vy1 = (y1 >= 0) && (y1 < HH);
        bool vx0 = (x0 >= 0) && (x0 < WW);
        bool vx1 = (x1 >= 0) && (x1 < WW);
        int cy0 = min(max(y0, 0), HH - 1), cy1 = min(max(y1, 0), HH - 1);
        int cx0 = min(max(x0, 0), WW - 1), cx1 = min(max(x1, 0), WW - 1);
        sIdx[t][x][0] = (cy0 * WW + cx0) * CC; sW[t][x][0] = (vy0 && vx0) ? wy0 * wx0 : 0.0f;
        sIdx[t][x][1] = (cy0 * WW + cx1) * CC; sW[t][x][1] = (vy0 && vx1) ? wy0 * wx1 : 0.0f;
        sIdx[t][x][2] = (cy1 * WW + cx0) * CC; sW[t][x][2] = (vy1 && vx0) ? wy1 * wx0 : 0.0f;
        sIdx[t][x][3] = (cy1 * WW + cx1) * CC; sW[t][x][3] = (vy1 && vx1) ? wy1 * wx1 : 0.0f;
    }
    __syncthreads();
    int lane = tid & 31, wrp = tid >> 5;   // 8 warps; warp owns x stripe
    for (int x = wrp; x < 56; x += 8) {
        float acc[8];
#pragma unroll
        for (int q = 0; q < 8; ++q) acc[q] = 0.0f;
#pragma unroll
        for (int t = 0; t < 9; ++t) {
            int i0 = sIdx[t][x][0], i1 = sIdx[t][x][1];
            int i2 = sIdx[t][x][2], i3 = sIdx[t][x][3];
            float w0 = sW[t][x][0], w1 = sW[t][x][1];
            float w2 = sW[t][x][2], w3 = sW[t][x][3];
#pragma unroll
            for (int q = 0; q < 8; ++q) {
                int c = q * 32 + lane;
                float v = w0 * Fn[i0 + c] + w1 * Fn[i1 + c]
                        + w2 * Fn[i2 + c] + w3 * Fn[i3 + c];
                acc[q] += sK[t][c] * v;
            }
        }
        float* o = Dn + ((size_t)y * WW + x) * CC;
#pragma unroll
        for (int q = 0; q < 8; ++q) o[q * 32 + lane] = acc[q];
    }
}

// ---------------------------------------------------------------------------
// 7) pw2 1x1 conv over concat(D0,D1) (K=512), NHWC input, NCHW output,
//    with global->register prefetch.
__global__ void __launch_bounds__(128) k_pw2(
    const float* __restrict__ D0, const float* __restrict__ D1,
    const float* __restrict__ wT, const float* __restrict__ bias,
    float* __restrict__ out)
{
    __shared__ __align__(16) float As[8][64];
    __shared__ __align__(16) float Bs[8][132];
    int tid = threadIdx.x;
    int tr = tid >> 4, tcn = tid & 15;
    int px0 = blockIdx.x * 128;
    int ocb = blockIdx.y * 64;
    int mypx = px0 + tid;

    unsigned long long acc2[4][8];
#pragma unroll
    for (int i = 0; i < 4; ++i)
#pragma unroll
        for (int j = 0; j < 8; ++j) acc2[i][j] = 0ULL;

    float4 v0, v1, v0N, v1N;
    float aReg[4], aRegN[4];
    {
        const float* src = D0 + (size_t)mypx * 256;
        v0 = *(const float4*)src;
        v1 = *(const float4*)(src + 4);
#pragma unroll
        for (int j = 0; j < 4; ++j)
            aReg[j] = wT[((tid >> 6) + j * 2) * 256 + ocb + (tid & 63)];
    }

    for (int t = 0; t < 64; ++t) {
        Bs[0][tid] = v0.x; Bs[1][tid] = v0.y; Bs[2][tid] = v0.z; Bs[3][tid] = v0.w;
        Bs[4][tid] = v1.x; Bs[5][tid] = v1.y; Bs[6][tid] = v1.z; Bs[7][tid] = v1.w;
#pragma unroll
        for (int j = 0; j < 4; ++j) {
            int rrow = (tid >> 6) + j * 2;
            As[rrow][tid & 63] = aReg[j];
        }
        __syncthreads();
        if (t + 1 < 64) {
            int k0 = (t + 1) * 8;
            const float* src = (k0 < 256) ? (D0 + (size_t)mypx * 256 + k0)
                                          : (D1 + (size_t)mypx * 256 + (k0 - 256));
            v0N = *(const float4*)src;
            v1N = *(const float4*)(src + 4);
#pragma unroll
            for (int j = 0; j < 4; ++j)
                aRegN[j] = wT[(k0 + (tid >> 6) + j * 2) * 256 + ocb + (tid & 63)];
        }
#pragma unroll
        for (int kk = 0; kk < 8; ++kk) {
            ulonglong2 ua0 = *(const ulonglong2*)&As[kk][tr * 8];
            ulonglong2 ua1 = *(const ulonglong2*)&As[kk][tr * 8 + 4];
            unsigned long long A2[4] = { ua0.x, ua0.y, ua1.x, ua1.y };
            float4 b0 = *(const float4*)&Bs[kk][tcn * 8];
            float4 b1 = *(const float4*)&Bs[kk][tcn * 8 + 4];
            float bv[8] = { b0.x, b0.y, b0.z, b0.w, b1.x, b1.y, b1.z, b1.w };
#pragma unroll
            for (int j = 0; j < 8; ++j) {
                unsigned long long bb = pack2(bv[j], bv[j]);
#pragma unroll
                for (int i2 = 0; i2 < 4; ++i2)
                    acc2[i2][j] = fma_f32x2(A2[i2], bb, acc2[i2][j]);
            }
        }
        __syncthreads();
        v0 = v0N; v1 = v1N;
#pragma unroll
        for (int j = 0; j < 4; ++j) aReg[j] = aRegN[j];
    }

#pragma unroll
    for (int i2 = 0; i2 < 4; ++i2) {
        int oc0 = ocb + tr * 8 + i2 * 2, oc1 = oc0 + 1;
        float bv0 = bias[oc0], bv1 = bias[oc1];
#pragma unroll
        for (int j = 0; j < 8; ++j) {
            float lo, hi; unpack2(acc2[i2][j], lo, hi);
            int px = px0 + tcn * 8 + j;
            int b2 = px / HWHW, s2 = px - b2 * HWHW;
            out[((size_t)b2 * CC + oc0) * HWHW + s2] = lo + bv0;
            out[((size_t)b2 * CC + oc1) * HWHW + s2] = hi + bv1;
        }
    }
}

// ---------------------------------------------------------------------------
// 8) BatchNorm (training-mode batch stats), two deterministic passes
__global__ void __launch_bounds__(256) k_bnred(
    const float* __restrict__ O, const float* __restrict__ gamma,
    const float* __restrict__ beta, float* __restrict__ stat)
{
    int c = blockIdx.x;
    float s = 0.0f, q = 0.0f;
    for (int i = threadIdx.x; i < NPIX; i += 256) {
        int b = i / HWHW, sp = i - b * HWHW;
        float v = O[((size_t)b * CC + c) * HWHW + sp];
        s += v; q += v * v;
    }
    __shared__ float ss[256], qq[256];
    ss[threadIdx.x] = s; qq[threadIdx.x] = q;
    __syncthreads();
    for (int st = 128; st > 0; st >>= 1) {
        if (threadIdx.x < st) {
            ss[threadIdx.x] += ss[threadIdx.x + st];
            qq[threadIdx.x] += qq[threadIdx.x + st];
        }
        __syncthreads();
    }
    if (threadIdx.x == 0) {
        float mean = ss[0] * (1.0f / (float)NPIX);
        float var  = qq[0] * (1.0f / (float)NPIX) - mean * mean;
        float sc = gamma[c] * rsqrtf(var + 1e-5f);
        stat[c] = sc;
        stat[256 + c] = beta[c] - mean * sc;
    }
}

__global__ void k_bnapp(float* __restrict__ O, const float* __restrict__ stat)
{
    int idx = (blockIdx.x * 256 + threadIdx.x) * 2;   // grid covers NF exactly
    float2 v = *(float2*)&O[idx];
    int c = (idx / HWHW) & 255;
    float scl = stat[c], sh = stat[256 + c];
    v.x = v.x * scl + sh;
    v.y = v.y * scl + sh;
    *(float2*)&O[idx] = v;
}

// ---------------------------------------------------------------------------
extern "C" void kernel_launch(void* const* d_in, const int* in_sizes, int n_in,
                              void* d_out, int out_size)
{
    const float* F_c    = (const float*)d_in[0];
    const float* dec_w  = (const float*)d_in[1];
    const float* dec_b  = (const float*)d_in[2];
    const float* off1_w = (const float*)d_in[3];
    const float* off1_b = (const float*)d_in[4];
    const float* off2_w = (const float*)d_in[5];
    const float* off2_b = (const float*)d_in[6];
    const float* akgdw  = (const float*)d_in[7];
    const float* hw     = (const float*)d_in[8];
    const float* hb     = (const float*)d_in[9];
    const float* pw2_w  = (const float*)d_in[10];
    const float* pw2_b  = (const float*)d_in[11];
    const float* gamma  = (const float*)d_in[12];
    const float* beta   = (const float*)d_in[13];
    float* out = (float*)d_out;

    float* sc = nullptr;
    cudaGetSymbolAddress((void**)&sc, g_scratch);

    float* F0   = sc;
    float* F1   = sc + (size_t)NF;
    float* F0n  = sc + (size_t)2 * NF;
    float* F1n  = sc + (size_t)3 * NF;
    float* D0   = sc + (size_t)4 * NF;
    float* D1   = sc + (size_t)5 * NF;
    float* h    = sc + (size_t)6 * NF;        // 2 * 1605632
    float* pp   = h + 3211264;                 // 2 * 451584
    float* wT1  = pp + 903168;                 // 2 * 147456
    float* wT2  = wT1 + 294912;                // 2 * 36864
    float* wTp  = wT2 + 73728;                 // 131072
    float* dvec = wTp + 131072;                // 4096
    float* Kb   = dvec + 4096;                 // 36864
    float* stat = Kb + 36864;                  // 512

    // 1) decouple (+ NHWC copies; replaces k_tr)
    k_decouple<<<98, 256>>>(F_c, dec_w, dec_b, F0, F1, F0n, F1n);

    // fused weight transposes
    int wtot = 2 * 2304 * 64 + 2 * 576 * 64 + 512 * 256;
    k_wtrans_all<<<(wtot + 255) / 256, 256>>>(off1_w, off2_w, pw2_w, wT1, wT2, wTp);

    // 2) offset generator convs (both regions per launch)
    dim3 g1(196, 2);
    k_conv3a<256, 64, true ><<<g1, 128>>>(F0, F1, wT1, off1_b, h, h + 1605632);
    k_conv3b< 64, 18, 32, 4, false><<<g1, 256>>>(h, h + 1605632, wT2, off2_b, pp, pp + 451584);

    // 4/5) AKG
    k_akgpool<<<4096, 64>>>(F0, F1, akgdw, dvec);
    k_akghead<<<dim3(8, 2), 256>>>(dvec, hw, hb, Kb);

    // 6) deformable dynamic depthwise
    k_deform<<<dim3(56, 8, 2), 256>>>(F0n, F1n, pp, pp + 451584, Kb, D0, D1);

    // 7) pointwise merge -> pre-BN output
    k_pw2<<<dim3(196, 4), 128>>>(D0, D1, wTp, pw2_b, out);

    // 8) BN (training-mode batch stats)
    k_bnred<<<256, 256>>>(out, gamma, beta, stat);
    k_bnapp<<<12544, 256>>>(out, stat);
}

// round 8
// speedup vs baseline: 1.1498x; 1.0183x over previous
#include <cuda_runtime.h>
#include <cuda_bf16.h>
#include <math.h>

// Problem constants (fixed shapes)
#define BB 8
#define CC 256
#define HH 56
#define WW 56
#define HWHW 3136            // 56*56
#define NPIX 25088           // B*H*W
#define NF 6422528           // B*C*H*W
#define RR 2
#define HID 64

// ---------------------------------------------------------------------------
// packed f32x2 helpers
__device__ __forceinline__ unsigned long long fma_f32x2(
    unsigned long long a, unsigned long long b, unsigned long long c)
{
    unsigned long long d;
    asm("fma.rn.f32x2 %0, %1, %2, %3;" : "=l"(d) : "l"(a), "l"(b), "l"(c));
    return d;
}
__device__ __forceinline__ unsigned long long pack2(float lo, float hi)
{
    unsigned long long d;
    asm("mov.b64 %0, {%1, %2};" : "=l"(d) : "f"(lo), "f"(hi));
    return d;
}
__device__ __forceinline__ void unpack2(unsigned long long v, float& lo, float& hi)
{
    asm("mov.b64 {%0, %1}, %2;" : "=f"(lo), "=f"(hi) : "l"(v));
}

// ---------------------------------------------------------------------------
// Scratch: single device global (no allocations allowed). ~173 MB.
__device__ __align__(16) float g_scratch[43200000];

// ---------------------------------------------------------------------------
// 1) TargetRegionDecoupler — also emits NHWC copies.
__global__ void __launch_bounds__(256) k_decouple(
    const float* __restrict__ F, const float* __restrict__ dw,
    const float* __restrict__ db, float* __restrict__ F0, float* __restrict__ F1,
    float* __restrict__ F0n, float* __restrict__ F1n)
{
    int p = blockIdx.x * 256 + threadIdx.x;
    if (p >= NPIX) return;
    int b = p / HWHW, s = p - b * HWHW;
    const float* base = F + (size_t)b * CC * HWHW + s;
    float l0 = db[0], l1 = db[1];
#pragma unroll 4
    for (int c = 0; c < CC; ++c) {
        float v = base[c * HWHW];
        l0 += v * dw[c];
        l1 += v * dw[CC + c];
    }
    float m0 = 1.0f / (1.0f + expf(l1 - l0));
    float m1 = 1.0f - m0;
    float* o0 = F0 + (size_t)b * CC * HWHW + s;
    float* o1 = F1 + (size_t)b * CC * HWHW + s;
    float* o0n = F0n + ((size_t)b * HWHW + s) * CC;
    float* o1n = F1n + ((size_t)b * HWHW + s) * CC;
    for (int c = 0; c < CC; c += 4) {
        float4 w0, w1;
        float v;
        v = base[(c + 0) * HWHW]; w0.x = v * (1.0f + m0); w1.x = v * (1.0f + m1);
        v = base[(c + 1) * HWHW]; w0.y = v * (1.0f + m0); w1.y = v * (1.0f + m1);
        v = base[(c + 2) * HWHW]; w0.z = v * (1.0f + m0); w1.z = v * (1.0f + m1);
        v = base[(c + 3) * HWHW]; w0.w = v * (1.0f + m0); w1.w = v * (1.0f + m1);
        o0[(c + 0) * HWHW] = w0.x; o0[(c + 1) * HWHW] = w0.y;
        o0[(c + 2) * HWHW] = w0.z; o0[(c + 3) * HWHW] = w0.w;
        o1[(c + 0) * HWHW] = w1.x; o1[(c + 1) * HWHW] = w1.y;
        o1[(c + 2) * HWHW] = w1.z; o1[(c + 3) * HWHW] = w1.w;
        *(float4*)&o0n[c] = w0;
        *(float4*)&o1n[c] = w1;
    }
}

// ---------------------------------------------------------------------------
// fused weight transposes:  w[OC][K] -> wT[K][64]  (zero-pad oc to 64)
__global__ void k_wtrans_all(
    const float* __restrict__ o1w, const float* __restrict__ o2w,
    const float* __restrict__ pww,
    float* __restrict__ wT1, float* __restrict__ wT2, float* __restrict__ wTp)
{
    int idx = blockIdx.x * 256 + threadIdx.x;
    if (idx < 2 * 2304 * 64) {
        int r = idx / (2304 * 64); int e = idx - r * 2304 * 64;
        int k = e / 64, oc = e - k * 64;
        wT1[idx] = (oc < 64) ? o1w[(size_t)r * 64 * 2304 + oc * 2304 + k] : 0.0f;
        return;
    }
    idx -= 2 * 2304 * 64;
    if (idx < 2 * 576 * 64) {
        int r = idx / (576 * 64); int e = idx - r * 576 * 64;
        int k = e / 64, oc = e - k * 64;
        wT2[r * 576 * 64 + e] = (oc < 18) ? o2w[(size_t)r * 18 * 576 + oc * 576 + k] : 0.0f;
        return;
    }
    idx -= 2 * 576 * 64;
    if (idx < 512 * 256) {
        int k = idx / 256, oc = idx - k * 256;
        wTp[idx] = pww[oc * 512 + k];
    }
}

// ---------------------------------------------------------------------------
// B-fragment loader (im2col on the fly) for 3x3 conv, pad=1
template<int IC>
__device__ __forceinline__ void conv_loadB(
    const float* __restrict__ inb, int my, int mx, int k0, float b[8])
{
#pragma unroll
    for (int j = 0; j < 8; ++j) {
        int k = k0 + j;
        int ic = k / 9, tap = k - ic * 9;
        int ky = tap / 3, kx = tap - ky * 3;
        int yy = my + ky - 1, xx = mx + kx - 1;
        float v = 0.0f;
        if ((unsigned)yy < (unsigned)HH && (unsigned)xx < (unsigned)WW)
            v = __ldg(&inb[ic * HWHW + yy * WW + xx]);
        b[j] = v;
    }
}

// ---------------------------------------------------------------------------
// 2a) conv1 partial: split-K implicit GEMM. 64oc x 128px tile, 128 threads,
//     8oc x 8px microtile + register prefetch. blockIdx.y=region,
//     blockIdx.z=k-slice (KSLICE k's each). No bias/relu; writes raw partials.
template<int IC, int KSLICE>
__global__ void __launch_bounds__(128) k_conv3p(
    const float* __restrict__ in0, const float* __restrict__ in1,
    const float* __restrict__ wTb, float* __restrict__ part)
{
    const int K = IC * 9;
    const int NT = KSLICE / 8;
    int r = blockIdx.y, z = blockIdx.z;
    int K0 = z * KSLICE;
    const float* in = r ? in1 : in0;
    const float* wT = wTb + (size_t)r * K * 64;
    float* out = part + (size_t)(z * 2 + r) * 1605632;   // [b][64][HWHW]

    __shared__ __align__(16) float As[8][64];
    __shared__ __align__(16) float Bs[8][132];
    int tid = threadIdx.x;
    int tr = tid >> 4, tcn = tid & 15;
    int px0 = blockIdx.x * 128;
    int mypx = px0 + tid;
    int mb = mypx / HWHW; int ms = mypx - mb * HWHW;
    int my = ms / WW, mx = ms - my * WW;
    const float* inb = in + (size_t)mb * IC * HWHW;

    unsigned long long acc2[4][8];
#pragma unroll
    for (int i = 0; i < 4; ++i)
#pragma unroll
        for (int j = 0; j < 8; ++j) acc2[i][j] = 0ULL;

    float bReg[8], aReg[4], bRegN[8], aRegN[4];
    conv_loadB<IC>(inb, my, mx, K0, bReg);
#pragma unroll
    for (int j = 0; j < 4; ++j)
        aReg[j] = wT[(K0 + (tid >> 6) + j * 2) * 64 + (tid & 63)];

    for (int t = 0; t < NT; ++t) {
#pragma unroll
        for (int j = 0; j < 8; ++j) Bs[j][tid] = bReg[j];
#pragma unroll
        for (int j = 0; j < 4; ++j) As[(tid >> 6) + j * 2][tid & 63] = aReg[j];
        __syncthreads();
        if (t + 1 < NT) {
            int k0 = K0 + (t + 1) * 8;
            conv_loadB<IC>(inb, my, mx, k0, bRegN);
#pragma unroll
            for (int j = 0; j < 4; ++j)
                aRegN[j] = wT[(k0 + (tid >> 6) + j * 2) * 64 + (tid & 63)];
        }
#pragma unroll
        for (int kk = 0; kk < 8; ++kk) {
            ulonglong2 ua0 = *(const ulonglong2*)&As[kk][tr * 8];
            ulonglong2 ua1 = *(const ulonglong2*)&As[kk][tr * 8 + 4];
            unsigned long long A2[4] = { ua0.x, ua0.y, ua1.x, ua1.y };
            float4 b0 = *(const float4*)&Bs[kk][tcn * 8];
            float4 b1 = *(const float4*)&Bs[kk][tcn * 8 + 4];
            float bv[8] = { b0.x, b0.y, b0.z, b0.w, b1.x, b1.y, b1.z, b1.w };
#pragma unroll
            for (int j = 0; j < 8; ++j) {
                unsigned long long bb = pack2(bv[j], bv[j]);
#pragma unroll
                for (int i2 = 0; i2 < 4; ++i2)
                    acc2[i2][j] = fma_f32x2(A2[i2], bb, acc2[i2][j]);
            }
        }
        __syncthreads();
#pragma unroll
        for (int j = 0; j < 8; ++j) bReg[j] = bRegN[j];
#pragma unroll
        for (int j = 0; j < 4; ++j) aReg[j] = aRegN[j];
    }

#pragma unroll
    for (int i2 = 0; i2 < 4; ++i2) {
        int oc0 = tr * 8 + i2 * 2, oc1 = oc0 + 1;
#pragma unroll
        for (int j = 0; j < 8; ++j) {
            float lo, hi; unpack2(acc2[i2][j], lo, hi);
            int px = px0 + tcn * 8 + j;
            int b2 = px / HWHW, s2 = px - b2 * HWHW;
            out[((size_t)b2 * 64 + oc0) * HWHW + s2] = lo;
            out[((size_t)b2 * 64 + oc1) * HWHW + s2] = hi;
        }
    }
}

// combine 4 k-slice partials + bias + relu -> h (2 regions back-to-back)
__global__ void __launch_bounds__(256) k_combine(
    const float* __restrict__ part, const float* __restrict__ biasb,
    float* __restrict__ h)
{
    int i = blockIdx.x * 256 + threadIdx.x;   // grid covers 2*1605632 exactly
    int r = i / 1605632; int e = i - r * 1605632;
    int oc = (e / HWHW) & 63;
    float v = part[(size_t)r * 1605632 + e]
            + part[(size_t)(2 + r) * 1605632 + e]
            + part[(size_t)(4 + r) * 1605632 + e]
            + part[(size_t)(6 + r) * 1605632 + e]
            + biasb[r * 64 + oc];
    h[i] = fmaxf(v, 0.0f);
}

// ---------------------------------------------------------------------------
// 2b) conv2: OCT oc x 128 px tile, 256 threads, 4oc x PXW px microtile + prefetch.
template<int IC, int OC, int OCT, int PXW, bool RELU>
__global__ void __launch_bounds__(256) k_conv3b(
    const float* __restrict__ in0, const float* __restrict__ in1,
    const float* __restrict__ wTb, const float* __restrict__ biasb,
    float* __restrict__ out0, float* __restrict__ out1)
{
    const int K = IC * 9;
    const int NT = K / 8;
    constexpr int PXG = 128 / PXW;
    static_assert((OCT / 4) * PXG == 256, "tile/thread mismatch");
    int r = blockIdx.y;
    const float* in   = r ? in1 : in0;
    const float* wT   = wTb + (size_t)r * K * 64;
    const float* bias = biasb + r * OC;
    float* out = r ? out1 : out0;

    __shared__ __align__(16) float As[8][OCT];
    __shared__ __align__(16) float Bs[8][132];

    int tid = threadIdx.x;
    int tcn = tid % PXG;
    int tr  = tid / PXG;
    int px0 = blockIdx.x * 128;
    int loadpx = tid & 127;
    int jh = tid >> 7;
    int mypx = px0 + loadpx;
    int mb = mypx / HWHW, ms = mypx - mb * HWHW;
    int my = ms / WW, mx = ms - my * WW;
    const float* inb = in + (size_t)mb * IC * HWHW;

    unsigned long long acc2[2][PXW];
#pragma unroll
    for (int i = 0; i < 2; ++i)
#pragma unroll
        for (int j = 0; j < PXW; ++j) acc2[i][j] = 0ULL;

    float bReg[4], aReg[OCT / 32], bRegN[4], aRegN[OCT / 32];
    {
#pragma unroll
        for (int jj = 0; jj < 4; ++jj) {
            int k = jh * 4 + jj;
            int ic = k / 9, tap = k - ic * 9;
            int ky = tap / 3, kx = tap - ky * 3;
            int yy = my + ky - 1, xx = mx + kx - 1;
            float v = 0.0f;
            if ((unsigned)yy < (unsigned)HH && (unsigned)xx < (unsigned)WW)
                v = __ldg(&inb[ic * HWHW + yy * WW + xx]);
            bReg[jj] = v;
        }
#pragma unroll
        for (int j = 0; j < OCT / 32; ++j) {
            int e = tid + j * 256;
            int row = e / OCT, oc = e % OCT;
            aReg[j] = wT[row * 64 + oc];
        }
    }

    for (int t = 0; t < NT; ++t) {
#pragma unroll
        for (int jj = 0; jj < 4; ++jj) Bs[jh * 4 + jj][loadpx] = bReg[jj];
#pragma unroll
        for (int j = 0; j < OCT / 32; ++j) {
            int e = tid + j * 256;
            int row = e / OCT, oc = e % OCT;
            As[row][oc] = aReg[j];
        }
        __syncthreads();
        if (t + 1 < NT) {
            int k0 = (t + 1) * 8;
#pragma unroll
            for (int jj = 0; jj < 4; ++jj) {
                int k = k0 + jh * 4 + jj;
                int ic = k / 9, tap = k - ic * 9;
                int ky = tap / 3, kx = tap - ky * 3;
                int yy = my + ky - 1, xx = mx + kx - 1;
                float v = 0.0f;
                if ((unsigned)yy < (unsigned)HH && (unsigned)xx < (unsigned)WW)
                    v = __ldg(&inb[ic * HWHW + yy * WW + xx]);
                bRegN[jj] = v;
            }
#pragma unroll
            for (int j = 0; j < OCT / 32; ++j) {
                int e = tid + j * 256;
                int row = e / OCT, oc = e % OCT;
                aRegN[j] = wT[(k0 + row) * 64 + oc];
            }
        }
#pragma unroll
        for (int kk = 0; kk < 8; ++kk) {
            ulonglong2 ua = *(const ulonglong2*)&As[kk][tr * 4];
            unsigned long long A2[2] = { ua.x, ua.y };
            float bv[PXW];
#pragma unroll
            for (int q = 0; q < PXW / 4; ++q) {
                float4 b4 = *(const float4*)&Bs[kk][tcn * PXW + q * 4];
                bv[q * 4 + 0] = b4.x; bv[q * 4 + 1] = b4.y;
                bv[q * 4 + 2] = b4.z; bv[q * 4 + 3] = b4.w;
            }
#pragma unroll
            for (int j = 0; j < PXW; ++j) {
                unsigned long long bb = pack2(bv[j], bv[j]);
                acc2[0][j] = fma_f32x2(A2[0], bb, acc2[0][j]);
                acc2[1][j] = fma_f32x2(A2[1], bb, acc2[1][j]);
            }
        }
        __syncthreads();
#pragma unroll
        for (int jj = 0; jj < 4; ++jj) bReg[jj] = bRegN[jj];
#pragma unroll
        for (int j = 0; j < OCT / 32; ++j) aReg[j] = aRegN[j];
    }

#pragma unroll
    for (int i2 = 0; i2 < 2; ++i2) {
        int oc0 = tr * 4 + i2 * 2, oc1 = oc0 + 1;
        float bv0 = (oc0 < OC) ? bias[oc0] : 0.0f;
        float bv1 = (oc1 < OC) ? bias[oc1] : 0.0f;
#pragma unroll
        for (int j = 0; j < PXW; ++j) {
            float lo, hi; unpack2(acc2[i2][j], lo, hi);
            int px = px0 + tcn * PXW + j;
            int b2 = px / HWHW, s2 = px - b2 * HWHW;
            if (oc0 < OC) {
                float v = lo + bv0; if (RELU) v = fmaxf(v, 0.0f);
                out[((size_t)b2 * OC + oc0) * HWHW + s2] = v;
            }
            if (oc1 < OC) {
                float v = hi + bv1; if (RELU) v = fmaxf(v, 0.0f);
                out[((size_t)b2 * OC + oc1) * HWHW + s2] = v;
            }
        }
    }
}

// ---------------------------------------------------------------------------
// 4) AKG part 1
__global__ void __launch_bounds__(64) k_akgpool(
    const float* __restrict__ F0, const float* __restrict__ F1,
    const float* __restrict__ dwwb, float* __restrict__ dvec)
{
    int gb = blockIdx.x; int r = gb >> 11; int bc = gb & 2047;
    int c = bc & 255;
    const float* P = (r ? F1 : F0) + (size_t)bc * HWHW;
    const float* dww = dwwb + r * CC * 9 + c * 9;
    __shared__ float pool[49];
    __shared__ float cnv[49];
    int t = threadIdx.x;
    if (t < 49) {
        int bi = t / 7, bj = t - bi * 7;
        const float* q = P + bi * 8 * WW + bj * 8;
        float sm = 0.0f;
#pragma unroll
        for (int u = 0; u < 8; ++u)
#pragma unroll
            for (int v = 0; v < 8; ++v) sm += q[u * WW + v];
        pool[t] = sm * 0.015625f;
    }
    __syncthreads();
    if (t < 49) {
        int pi = t / 7, pj = t - pi * 7;
        float sm = 0.0f;
#pragma unroll
        for (int u = 0; u < 3; ++u)
#pragma unroll
            for (int v = 0; v < 3; ++v) {
                int yy = pi + u - 1, xx = pj + v - 1;
                if ((unsigned)yy < 7u && (unsigned)xx < 7u)
                    sm += dww[u * 3 + v] * pool[yy * 7 + xx];
            }
        cnv[t] = fmaxf(sm, 0.0f);
    }
    __syncthreads();
    if (t == 0) {
        float sm = 0.0f;
        for (int i = 0; i < 49; ++i) sm += cnv[i];
        dvec[r * 2048 + bc] = sm * (1.0f / 49.0f);
    }
}

// 5) AKG part 2: 1x1 head (2304x256) + tanh
__global__ void __launch_bounds__(256) k_akghead(
    const float* __restrict__ dvec, const float* __restrict__ hwb,
    const float* __restrict__ hbb, float* __restrict__ Kout)
{
    int b = blockIdx.x, r = blockIdx.y;
    const float* hw = hwb + (size_t)r * 2304 * 256;
    const float* hb = hbb + r * 2304;
    __shared__ float dv[256];
    dv[threadIdx.x] = dvec[r * 2048 + b * 256 + threadIdx.x];
    __syncthreads();
    for (int oc = threadIdx.x; oc < 2304; oc += 256) {
        const float* w = hw + (size_t)oc * 256;
        float sm = hb[oc];
#pragma unroll 8
        for (int c2 = 0; c2 < 256; ++c2) sm += w[c2] * dv[c2];
        Kout[(r * 8 + b) * 2304 + oc] = tanhf(sm);
    }
}

// ---------------------------------------------------------------------------
// 6) dynamic depthwise deformable conv (NHWC gather).
__global__ void __launch_bounds__(256) k_deform(
    const float* __restrict__ F0n, const float* __restrict__ F1n,
    const float* __restrict__ p0, const float* __restrict__ p1,
    const float* __restrict__ Kall, float* __restrict__ D0, float* __restrict__ D1)
{
    int y = blockIdx.x, b = blockIdx.y, r = blockIdx.z;
    const float* Fn = (r ? F1n : F0n) + (size_t)b * HWHW * CC;
    const float* off = (r ? p1 : p0) + (size_t)b * 18 * HWHW;
    const float* Kw = Kall + (r * 8 + b) * 2304;
    float* Dn = (r ? D1 : D0) + (size_t)b * HWHW * CC;

    __shared__ int   sIdx[9][56][4];
    __shared__ float sW[9][56][4];
    __shared__ float sK[9][256];
    int tid = threadIdx.x;
    for (int i = tid; i < 2304; i += 256) {
        int c = i / 9, t = i - c * 9;
        sK[t][c] = Kw[i];
    }
    for (int i = tid; i < 504; i += 256) {
        int t = i / 56, x = i - t * 56;
        int ky = t / 3, kx = t - ky * 3;
        float dy = off[(2 * t) * HWHW + y * WW + x];
        float dx = off[(2 * t + 1) * HWHW + y * WW + x];
        float py = (float)(y + ky - 1) + dy;
        float px = (float)(x + kx - 1) + dx;
        float fy = floorf(py), fx = floorf(px);
        float wy1 = py - fy, wx1 = px - fx;
        float wy0 = 1.0f - wy1, wx0 = 1.0f - wx1;
        int y0 = (int)fy, x0 = (int)fx;
        int y1 = y0 + 1, x1 = x0 + 1;
        bool vy0 = (y0 >= 0) && (y0 < HH);
        bool vy1 = (y1 >= 0) && (y1 < HH);
        bool vx0 = (x0 >= 0) && (x0 < WW);
        bool vx1 = (x1 >= 0) && (x1 < WW);
        int cy0 = min(max(y0, 0), HH - 1), cy1 = min(max(y1, 0), HH - 1);
        int cx0 = min(max(x0, 0), WW - 1), cx1 = min(max(x1, 0), WW - 1);
        sIdx[t][x][0] = (cy0 * WW + cx0) * CC; sW[t][x][0] = (vy0 && vx0) ? wy0 * wx0 : 0.0f;
        sIdx[t][x][1] = (cy0 * WW + cx1) * CC; sW[t][x][1] = (vy0 && vx1) ? wy0 * wx1 : 0.0f;
        sIdx[t][x][2] = (cy1 * WW + cx0) * CC; sW[t][x][2] = (vy1 && vx0) ? wy1 * wx0 : 0.0f;
        sIdx[t][x][3] = (cy1 * WW + cx1) * CC; sW[t][x][3] = (vy1 && vx1) ? wy1 * wx1 : 0.0f;
    }
    __syncthreads();
    int lane = tid & 31, wrp = tid >> 5;   // 8 warps; warp owns x stripe
    for (int x = wrp; x < 56; x += 8) {
        float acc[8];
#pragma unroll
        for (int q = 0; q < 8; ++q) acc[q] = 0.0f;
#pragma unroll
        for (int t = 0; t < 9; ++t) {
            int i0 = sIdx[t][x][0], i1 = sIdx[t][x][1];
            int i2 = sIdx[t][x][2], i3 = sIdx[t][x][3];
            float w0 = sW[t][x][0], w1 = sW[t][x][1];
            float w2 = sW[t][x][2], w3 = sW[t][x][3];
#pragma unroll
            for (int q = 0; q < 8; ++q) {
                int c = q * 32 + lane;
                float v = w0 * Fn[i0 + c] + w1 * Fn[i1 + c]
                        + w2 * Fn[i2 + c] + w3 * Fn[i3 + c];
                acc[q] += sK[t][c] * v;
            }
        }
        float* o = Dn + ((size_t)y * WW + x) * CC;
#pragma unroll
        for (int q = 0; q < 8; ++q) o[q * 32 + lane] = acc[q];
    }
}

// ---------------------------------------------------------------------------
// 7) pw2 1x1 conv over concat(D0,D1) (K=512), NHWC input, NCHW output,
//    with global->register prefetch.
__global__ void __launch_bounds__(128) k_pw2(
    const float* __restrict__ D0, const float* __restrict__ D1,
    const float* __restrict__ wT, const float* __restrict__ bias,
    float* __restrict__ out)
{
    __shared__ __align__(16) float As[8][64];
    __shared__ __align__(16) float Bs[8][132];
    int tid = threadIdx.x;
    int tr = tid >> 4, tcn = tid & 15;
    int px0 = blockIdx.x * 128;
    int ocb = blockIdx.y * 64;
    int mypx = px0 + tid;

    unsigned long long acc2[4][8];
#pragma unroll
    for (int i = 0; i < 4; ++i)
#pragma unroll
        for (int j = 0; j < 8; ++j) acc2[i][j] = 0ULL;

    float4 v0, v1, v0N, v1N;
    float aReg[4], aRegN[4];
    {
        const float* src = D0 + (size_t)mypx * 256;
        v0 = *(const float4*)src;
        v1 = *(const float4*)(src + 4);
#pragma unroll
        for (int j = 0; j < 4; ++j)
            aReg[j] = wT[((tid >> 6) + j * 2) * 256 + ocb + (tid & 63)];
    }

    for (int t = 0; t < 64; ++t) {
        Bs[0][tid] = v0.x; Bs[1][tid] = v0.y; Bs[2][tid] = v0.z; Bs[3][tid] = v0.w;
        Bs[4][tid] = v1.x; Bs[5][tid] = v1.y; Bs[6][tid] = v1.z; Bs[7][tid] = v1.w;
#pragma unroll
        for (int j = 0; j < 4; ++j) {
            int rrow = (tid >> 6) + j * 2;
            As[rrow][tid & 63] = aReg[j];
        }
        __syncthreads();
        if (t + 1 < 64) {
            int k0 = (t + 1) * 8;
            const float* src = (k0 < 256) ? (D0 + (size_t)mypx * 256 + k0)
                                          : (D1 + (size_t)mypx * 256 + (k0 - 256));
            v0N = *(const float4*)src;
            v1N = *(const float4*)(src + 4);
#pragma unroll
            for (int j = 0; j < 4; ++j)
                aRegN[j] = wT[(k0 + (tid >> 6) + j * 2) * 256 + ocb + (tid & 63)];
        }
#pragma unroll
        for (int kk = 0; kk < 8; ++kk) {
            ulonglong2 ua0 = *(const ulonglong2*)&As[kk][tr * 8];
            ulonglong2 ua1 = *(const ulonglong2*)&As[kk][tr * 8 + 4];
            unsigned long long A2[4] = { ua0.x, ua0.y, ua1.x, ua1.y };
            float4 b0 = *(const float4*)&Bs[kk][tcn * 8];
            float4 b1 = *(const float4*)&Bs[kk][tcn * 8 + 4];
            float bv[8] = { b0.x, b0.y, b0.z, b0.w, b1.x, b1.y, b1.z, b1.w };
#pragma unroll
            for (int j = 0; j < 8; ++j) {
                unsigned long long bb = pack2(bv[j], bv[j]);
#pragma unroll
                for (int i2 = 0; i2 < 4; ++i2)
                    acc2[i2][j] = fma_f32x2(A2[i2], bb, acc2[i2][j]);
            }
        }
        __syncthreads();
        v0 = v0N; v1 = v1N;
#pragma unroll
        for (int j = 0; j < 4; ++j) aReg[j] = aRegN[j];
    }

#pragma unroll
    for (int i2 = 0; i2 < 4; ++i2) {
        int oc0 = ocb + tr * 8 + i2 * 2, oc1 = oc0 + 1;
        float bv0 = bias[oc0], bv1 = bias[oc1];
#pragma unroll
        for (int j = 0; j < 8; ++j) {
            float lo, hi; unpack2(acc2[i2][j], lo, hi);
            int px = px0 + tcn * 8 + j;
            int b2 = px / HWHW, s2 = px - b2 * HWHW;
            out[((size_t)b2 * CC + oc0) * HWHW + s2] = lo + bv0;
            out[((size_t)b2 * CC + oc1) * HWHW + s2] = hi + bv1;
        }
    }
}

// ---------------------------------------------------------------------------
// 8) BatchNorm (training-mode batch stats), two deterministic passes
__global__ void __launch_bounds__(256) k_bnred(
    const float* __restrict__ O, const float* __restrict__ gamma,
    const float* __restrict__ beta, float* __restrict__ stat)
{
    int c = blockIdx.x;
    float s = 0.0f, q = 0.0f;
    for (int i = threadIdx.x; i < NPIX; i += 256) {
        int b = i / HWHW, sp = i - b * HWHW;
        float v = O[((size_t)b * CC + c) * HWHW + sp];
        s += v; q += v * v;
    }
    __shared__ float ss[256], qq[256];
    ss[threadIdx.x] = s; qq[threadIdx.x] = q;
    __syncthreads();
    for (int st = 128; st > 0; st >>= 1) {
        if (threadIdx.x < st) {
            ss[threadIdx.x] += ss[threadIdx.x + st];
            qq[threadIdx.x] += qq[threadIdx.x + st];
        }
        __syncthreads();
    }
    if (threadIdx.x == 0) {
        float mean = ss[0] * (1.0f / (float)NPIX);
        float var  = qq[0] * (1.0f / (float)NPIX) - mean * mean;
        float sc = gamma[c] * rsqrtf(var + 1e-5f);
        stat[c] = sc;
        stat[256 + c] = beta[c] - mean * sc;
    }
}

__global__ void k_bnapp(float* __restrict__ O, const float* __restrict__ stat)
{
    int idx = (blockIdx.x * 256 + threadIdx.x) * 2;   // grid covers NF exactly
    float2 v = *(float2*)&O[idx];
    int c = (idx / HWHW) & 255;
    float scl = stat[c], sh = stat[256 + c];
    v.x = v.x * scl + sh;
    v.y = v.y * scl + sh;
    *(float2*)&O[idx] = v;
}

// ---------------------------------------------------------------------------
extern "C" void kernel_launch(void* const* d_in, const int* in_sizes, int n_in,
                              void* d_out, int out_size)
{
    const float* F_c    = (const float*)d_in[0];
    const float* dec_w  = (const float*)d_in[1];
    const float* dec_b  = (const float*)d_in[2];
    const float* off1_w = (const float*)d_in[3];
    const float* off1_b = (const float*)d_in[4];
    const float* off2_w = (const float*)d_in[5];
    const float* off2_b = (const float*)d_in[6];
    const float* akgdw  = (const float*)d_in[7];
    const float* hw     = (const float*)d_in[8];
    const float* hb     = (const float*)d_in[9];
    const float* pw2_w  = (const float*)d_in[10];
    const float* pw2_b  = (const float*)d_in[11];
    const float* gamma  = (const float*)d_in[12];
    const float* beta   = (const float*)d_in[13];
    float* out = (float*)d_out;

    float* sc = nullptr;
    cudaGetSymbolAddress((void**)&sc, g_scratch);

    float* F0   = sc;
    float* F1   = sc + (size_t)NF;
    float* F0n  = sc + (size_t)2 * NF;
    float* F1n  = sc + (size_t)3 * NF;
    float* D0   = sc + (size_t)4 * NF;    // also conv1 partial scratch (8 x 1605632)
    float* D1   = sc + (size_t)5 * NF;
    float* h    = sc + (size_t)6 * NF;        // 2 * 1605632
    float* pp   = h + 3211264;                 // 2 * 451584
    float* wT1  = pp + 903168;                 // 2 * 147456
    float* wT2  = wT1 + 294912;                // 2 * 36864
    float* wTp  = wT2 + 73728;                 // 131072
    float* dvec = wTp + 131072;                // 4096
    float* Kb   = dvec + 4096;                 // 36864
    float* stat = Kb + 36864;                  // 512

    // 1) decouple (+ NHWC copies)
    k_decouple<<<98, 256>>>(F_c, dec_w, dec_b, F0, F1, F0n, F1n);

    // fused weight transposes
    int wtot = 2 * 2304 * 64 + 2 * 576 * 64 + 512 * 256;
    k_wtrans_all<<<(wtot + 255) / 256, 256>>>(off1_w, off2_w, pw2_w, wT1, wT2, wTp);

    // 2) conv1 split-K (4 slices of 576) -> partials in D0/D1 space, combine -> h
    k_conv3p<256, 576><<<dim3(196, 2, 4), 128>>>(F0, F1, wT1, D0);
    k_combine<<<12544, 256>>>(D0, off1_b, h);
    // conv2
    k_conv3b<64, 18, 32, 4, false><<<dim3(196, 2), 256>>>(h, h + 1605632, wT2, off2_b, pp, pp + 451584);

    // 4/5) AKG
    k_akgpool<<<4096, 64>>>(F0, F1, akgdw, dvec);
    k_akghead<<<dim3(8, 2), 256>>>(dvec, hw, hb, Kb);

    // 6) deformable dynamic depthwise (overwrites partial scratch — safe, combine done)
    k_deform<<<dim3(56, 8, 2), 256>>>(F0n, F1n, pp, pp + 451584, Kb, D0, D1);

    // 7) pointwise merge -> pre-BN output
    k_pw2<<<dim3(196, 4), 128>>>(D0, D1, wTp, pw2_b, out);

    // 8) BN (training-mode batch stats)
    k_bnred<<<256, 256>>>(out, gamma, beta, stat);
    k_bnapp<<<12544, 256>>>(out, stat);
}

// round 9
// speedup vs baseline: 1.3565x; 1.1798x over previous
#include <cuda_runtime.h>
#include <cuda_bf16.h>
#include <math.h>
#include <stdint.h>

// Problem constants (fixed shapes)
#define BB 8
#define CC 256
#define HH 56
#define WW 56
#define HWHW 3136            // 56*56
#define NPIX 25088           // B*H*W
#define NF 6422528           // B*C*H*W
#define RR 2
#define HID 64

// ---------------------------------------------------------------------------
// packed f32x2 helpers
__device__ __forceinline__ unsigned long long fma_f32x2(
    unsigned long long a, unsigned long long b, unsigned long long c)
{
    unsigned long long d;
    asm("fma.rn.f32x2 %0, %1, %2, %3;" : "=l"(d) : "l"(a), "l"(b), "l"(c));
    return d;
}
__device__ __forceinline__ unsigned long long pack2(float lo, float hi)
{
    unsigned long long d;
    asm("mov.b64 %0, {%1, %2};" : "=l"(d) : "f"(lo), "f"(hi));
    return d;
}
__device__ __forceinline__ void unpack2(unsigned long long v, float& lo, float& hi)
{
    asm("mov.b64 {%0, %1}, %2;" : "=f"(lo), "=f"(hi) : "l"(v));
}
__device__ __forceinline__ uint32_t to_tf32(float v)
{
    uint32_t u;
    asm("cvt.rna.tf32.f32 %0, %1;" : "=r"(u) : "f"(v));
    return u;
}

// ---------------------------------------------------------------------------
// Scratch: single device global (no allocations allowed). ~173 MB.
__device__ __align__(16) float g_scratch[43200000];

// ---------------------------------------------------------------------------
// 1) TargetRegionDecoupler — also emits NHWC copies.
__global__ void __launch_bounds__(256) k_decouple(
    const float* __restrict__ F, const float* __restrict__ dw,
    const float* __restrict__ db, float* __restrict__ F0, float* __restrict__ F1,
    float* __restrict__ F0n, float* __restrict__ F1n)
{
    int p = blockIdx.x * 256 + threadIdx.x;
    if (p >= NPIX) return;
    int b = p / HWHW, s = p - b * HWHW;
    const float* base = F + (size_t)b * CC * HWHW + s;
    float l0 = db[0], l1 = db[1];
#pragma unroll 4
    for (int c = 0; c < CC; ++c) {
        float v = base[c * HWHW];
        l0 += v * dw[c];
        l1 += v * dw[CC + c];
    }
    float m0 = 1.0f / (1.0f + expf(l1 - l0));
    float m1 = 1.0f - m0;
    float* o0 = F0 + (size_t)b * CC * HWHW + s;
    float* o1 = F1 + (size_t)b * CC * HWHW + s;
    float* o0n = F0n + ((size_t)b * HWHW + s) * CC;
    float* o1n = F1n + ((size_t)b * HWHW + s) * CC;
    for (int c = 0; c < CC; c += 4) {
        float4 w0, w1;
        float v;
        v = base[(c + 0) * HWHW]; w0.x = v * (1.0f + m0); w1.x = v * (1.0f + m1);
        v = base[(c + 1) * HWHW]; w0.y = v * (1.0f + m0); w1.y = v * (1.0f + m1);
        v = base[(c + 2) * HWHW]; w0.z = v * (1.0f + m0); w1.z = v * (1.0f + m1);
        v = base[(c + 3) * HWHW]; w0.w = v * (1.0f + m0); w1.w = v * (1.0f + m1);
        o0[(c + 0) * HWHW] = w0.x; o0[(c + 1) * HWHW] = w0.y;
        o0[(c + 2) * HWHW] = w0.z; o0[(c + 3) * HWHW] = w0.w;
        o1[(c + 0) * HWHW] = w1.x; o1[(c + 1) * HWHW] = w1.y;
        o1[(c + 2) * HWHW] = w1.z; o1[(c + 3) * HWHW] = w1.w;
        *(float4*)&o0n[c] = w0;
        *(float4*)&o1n[c] = w1;
    }
}

// ---------------------------------------------------------------------------
// fused weight transposes.  wT1 is stored PRE-ROUNDED to tf32 (bit pattern in
// a float slot) for the tensor-core conv1.  wT2/wTp stay fp32.
__global__ void k_wtrans_all(
    const float* __restrict__ o1w, const float* __restrict__ o2w,
    const float* __restrict__ pww,
    float* __restrict__ wT1, float* __restrict__ wT2, float* __restrict__ wTp)
{
    int idx = blockIdx.x * 256 + threadIdx.x;
    if (idx < 2 * 2304 * 64) {
        int r = idx / (2304 * 64); int e = idx - r * 2304 * 64;
        int k = e / 64, oc = e - k * 64;
        float v = (oc < 64) ? o1w[(size_t)r * 64 * 2304 + oc * 2304 + k] : 0.0f;
        wT1[idx] = __uint_as_float(to_tf32(v));
        return;
    }
    idx -= 2 * 2304 * 64;
    if (idx < 2 * 576 * 64) {
        int r = idx / (576 * 64); int e = idx - r * 576 * 64;
        int k = e / 64, oc = e - k * 64;
        wT2[r * 576 * 64 + e] = (oc < 18) ? o2w[(size_t)r * 18 * 576 + oc * 576 + k] : 0.0f;
        return;
    }
    idx -= 2 * 576 * 64;
    if (idx < 512 * 256) {
        int k = idx / 256, oc = idx - k * 256;
        wTp[idx] = pww[oc * 512 + k];
    }
}

// ---------------------------------------------------------------------------
// 2a) conv1 via tf32 mma.sync.m16n8k8.  64oc x 128px tile, 256 threads,
//     8 warps = 4 m-tiles x 2 n-halves; each warp: m16 x n64 (8 mma tiles).
//     K staged through smem in chunks of 32.  Bias+ReLU fused.
__global__ void __launch_bounds__(256) k_conv1t(
    const float* __restrict__ in0, const float* __restrict__ in1,
    const float* __restrict__ wTb, const float* __restrict__ biasb,
    float* __restrict__ out0, float* __restrict__ out1)
{
    const int K = 2304;
    int r = blockIdx.y;
    const float* in = r ? in1 : in0;
    const uint32_t* wT = (const uint32_t*)wTb + (size_t)r * K * 64;
    const float* bias = biasb + r * 64;
    float* out = r ? out1 : out0;

    // pads chosen so pad % 32 == 8 -> fragment LDS are conflict-free
    __shared__ __align__(16) uint32_t As[32][72];
    __shared__ __align__(16) uint32_t Bs[32][136];

    int tid = threadIdx.x;
    int lane = tid & 31, wid = tid >> 5;
    int mw = wid & 3;          // oc tile: 16*mw
    int nw = wid >> 2;         // px half: 64*nw
    int g = lane >> 2, tig = lane & 3;

    int px0 = blockIdx.x * 128;
    int loadpx = tid & 127;    // B loader: this pixel column
    int khalf = tid >> 7;      // rows [khalf*16, khalf*16+16) of the chunk
    int mypx = px0 + loadpx;
    int mb = mypx / HWHW, ms = mypx - mb * HWHW;
    int my = ms / WW, mx = ms - my * WW;
    const float* inb = in + (size_t)mb * CC * HWHW;

    float acc[8][4];
#pragma unroll
    for (int i = 0; i < 8; ++i)
#pragma unroll
        for (int j = 0; j < 4; ++j) acc[i][j] = 0.0f;

    int arow = tid >> 3;             // A loader: row 0..31
    int acol = (tid & 7) * 8;        // 8 consecutive oc

    for (int kc = 0; kc < K; kc += 32) {
        // A: 32x64 tf32 (already rounded), vectorized
        {
            const uint4* src = (const uint4*)(wT + (size_t)(kc + arow) * 64 + acol);
            uint4 v0 = src[0], v1 = src[1];
            *(uint4*)&As[arow][acol] = v0;
            *(uint4*)&As[arow][acol + 4] = v1;
        }
        // B: im2col 16 k-rows for my pixel, cvt to tf32
        {
            int kk = kc + khalf * 16;
            int ic = kk / 9;
            int tq = kk - ic * 9;
            int ky = tq / 3;
            int kx = tq - ky * 3;
#pragma unroll
            for (int jj = 0; jj < 16; ++jj) {
                int yy = my + ky - 1, xx = mx + kx - 1;
                float v = 0.0f;
                if ((unsigned)yy < (unsigned)HH && (unsigned)xx < (unsigned)WW)
                    v = __ldg(&inb[ic * HWHW + yy * WW + xx]);
                Bs[khalf * 16 + jj][loadpx] = to_tf32(v);
                // advance (ky,kx,ic)
                ++kx;
                if (kx == 3) { kx = 0; ++ky; if (ky == 3) { ky = 0; ++ic; } }
            }
        }
        __syncthreads();
#pragma unroll
        for (int ks = 0; ks < 4; ++ks) {
            int k0 = ks * 8;
            uint32_t a0 = As[k0 + tig][mw * 16 + g];
            uint32_t a1 = As[k0 + tig][mw * 16 + g + 8];
            uint32_t a2 = As[k0 + tig + 4][mw * 16 + g];
            uint32_t a3 = As[k0 + tig + 4][mw * 16 + g + 8];
#pragma unroll
            for (int nt = 0; nt < 8; ++nt) {
                int n0 = nw * 64 + nt * 8;
                uint32_t b0 = Bs[k0 + tig][n0 + g];
                uint32_t b1 = Bs[k0 + tig + 4][n0 + g];
                asm volatile(
                    "mma.sync.aligned.m16n8k8.row.col.f32.tf32.tf32.f32 "
                    "{%0,%1,%2,%3}, {%4,%5,%6,%7}, {%8,%9}, {%0,%1,%2,%3};"
                    : "+f"(acc[nt][0]), "+f"(acc[nt][1]),
                      "+f"(acc[nt][2]), "+f"(acc[nt][3])
                    : "r"(a0), "r"(a1), "r"(a2), "r"(a3), "r"(b0), "r"(b1));
            }
        }
        __syncthreads();
    }

    // epilogue: c0:(g, 2tig) c1:(g, 2tig+1) c2:(g+8, 2tig) c3:(g+8, 2tig+1)
    int oc_lo = mw * 16 + g;
    float bv_lo = bias[oc_lo];
    float bv_hi = bias[oc_lo + 8];
#pragma unroll
    for (int nt = 0; nt < 8; ++nt) {
        int pxa = px0 + nw * 64 + nt * 8 + 2 * tig;
        {
            int b2 = pxa / HWHW, s2 = pxa - b2 * HWHW;
            out[((size_t)b2 * 64 + oc_lo) * HWHW + s2] = fmaxf(acc[nt][0] + bv_lo, 0.0f);
            out[((size_t)b2 * 64 + oc_lo + 8) * HWHW + s2] = fmaxf(acc[nt][2] + bv_hi, 0.0f);
        }
        {
            int pxb = pxa + 1;
            int b2 = pxb / HWHW, s2 = pxb - b2 * HWHW;
            out[((size_t)b2 * 64 + oc_lo) * HWHW + s2] = fmaxf(acc[nt][1] + bv_lo, 0.0f);
            out[((size_t)b2 * 64 + oc_lo + 8) * HWHW + s2] = fmaxf(acc[nt][3] + bv_hi, 0.0f);
        }
    }
}

// ---------------------------------------------------------------------------
// 2b) conv2: OCT oc x 128 px tile, 256 threads, 4oc x PXW px microtile + prefetch.
template<int IC, int OC, int OCT, int PXW, bool RELU>
__global__ void __launch_bounds__(256) k_conv3b(
    const float* __restrict__ in0, const float* __restrict__ in1,
    const float* __restrict__ wTb, const float* __restrict__ biasb,
    float* __restrict__ out0, float* __restrict__ out1)
{
    const int K = IC * 9;
    const int NT = K / 8;
    constexpr int PXG = 128 / PXW;
    static_assert((OCT / 4) * PXG == 256, "tile/thread mismatch");
    int r = blockIdx.y;
    const float* in   = r ? in1 : in0;
    const float* wT   = wTb + (size_t)r * K * 64;
    const float* bias = biasb + r * OC;
    float* out = r ? out1 : out0;

    __shared__ __align__(16) float As[8][OCT];
    __shared__ __align__(16) float Bs[8][132];

    int tid = threadIdx.x;
    int tcn = tid % PXG;
    int tr  = tid / PXG;
    int px0 = blockIdx.x * 128;
    int loadpx = tid & 127;
    int jh = tid >> 7;
    int mypx = px0 + loadpx;
    int mb = mypx / HWHW, ms = mypx - mb * HWHW;
    int my = ms / WW, mx = ms - my * WW;
    const float* inb = in + (size_t)mb * IC * HWHW;

    unsigned long long acc2[2][PXW];
#pragma unroll
    for (int i = 0; i < 2; ++i)
#pragma unroll
        for (int j = 0; j < PXW; ++j) acc2[i][j] = 0ULL;

    float bReg[4], aReg[OCT / 32], bRegN[4], aRegN[OCT / 32];
    {
#pragma unroll
        for (int jj = 0; jj < 4; ++jj) {
            int k = jh * 4 + jj;
            int ic = k / 9, tap = k - ic * 9;
            int ky = tap / 3, kx = tap - ky * 3;
            int yy = my + ky - 1, xx = mx + kx - 1;
            float v = 0.0f;
            if ((unsigned)yy < (unsigned)HH && (unsigned)xx < (unsigned)WW)
                v = __ldg(&inb[ic * HWHW + yy * WW + xx]);
            bReg[jj] = v;
        }
#pragma unroll
        for (int j = 0; j < OCT / 32; ++j) {
            int e = tid + j * 256;
            int row = e / OCT, oc = e % OCT;
            aReg[j] = wT[row * 64 + oc];
        }
    }

    for (int t = 0; t < NT; ++t) {
#pragma unroll
        for (int jj = 0; jj < 4; ++jj) Bs[jh * 4 + jj][loadpx] = bReg[jj];
#pragma unroll
        for (int j = 0; j < OCT / 32; ++j) {
            int e = tid + j * 256;
            int row = e / OCT, oc = e % OCT;
            As[row][oc] = aReg[j];
        }
        __syncthreads();
        if (t + 1 < NT) {
            int k0 = (t + 1) * 8;
#pragma unroll
            for (int jj = 0; jj < 4; ++jj) {
                int k = k0 + jh * 4 + jj;
                int ic = k / 9, tap = k - ic * 9;
                int ky = tap / 3, kx = tap - ky * 3;
                int yy = my + ky - 1, xx = mx + kx - 1;
                float v = 0.0f;
                if ((unsigned)yy < (unsigned)HH && (unsigned)xx < (unsigned)WW)
                    v = __ldg(&inb[ic * HWHW + yy * WW + xx]);
                bRegN[jj] = v;
            }
#pragma unroll
            for (int j = 0; j < OCT / 32; ++j) {
                int e = tid + j * 256;
                int row = e / OCT, oc = e % OCT;
                aRegN[j] = wT[(k0 + row) * 64 + oc];
            }
        }
#pragma unroll
        for (int kk = 0; kk < 8; ++kk) {
            ulonglong2 ua = *(const ulonglong2*)&As[kk][tr * 4];
            unsigned long long A2[2] = { ua.x, ua.y };
            float bv[PXW];
#pragma unroll
            for (int q = 0; q < PXW / 4; ++q) {
                float4 b4 = *(const float4*)&Bs[kk][tcn * PXW + q * 4];
                bv[q * 4 + 0] = b4.x; bv[q * 4 + 1] = b4.y;
                bv[q * 4 + 2] = b4.z; bv[q * 4 + 3] = b4.w;
            }
#pragma unroll
            for (int j = 0; j < PXW; ++j) {
                unsigned long long bb = pack2(bv[j], bv[j]);
                acc2[0][j] = fma_f32x2(A2[0], bb, acc2[0][j]);
                acc2[1][j] = fma_f32x2(A2[1], bb, acc2[1][j]);
            }
        }
        __syncthreads();
#pragma unroll
        for (int jj = 0; jj < 4; ++jj) bReg[jj] = bRegN[jj];
#pragma unroll
        for (int j = 0; j < OCT / 32; ++j) aReg[j] = aRegN[j];
    }

#pragma unroll
    for (int i2 = 0; i2 < 2; ++i2) {
        int oc0 = tr * 4 + i2 * 2, oc1 = oc0 + 1;
        float bv0 = (oc0 < OC) ? bias[oc0] : 0.0f;
        float bv1 = (oc1 < OC) ? bias[oc1] : 0.0f;
#pragma unroll
        for (int j = 0; j < PXW; ++j) {
            float lo, hi; unpack2(acc2[i2][j], lo, hi);
            int px = px0 + tcn * PXW + j;
            int b2 = px / HWHW, s2 = px - b2 * HWHW;
            if (oc0 < OC) {
                float v = lo + bv0; if (RELU) v = fmaxf(v, 0.0f);
                out[((size_t)b2 * OC + oc0) * HWHW + s2] = v;
            }
            if (oc1 < OC) {
                float v = hi + bv1; if (RELU) v = fmaxf(v, 0.0f);
                out[((size_t)b2 * OC + oc1) * HWHW + s2] = v;
            }
        }
    }
}

// ---------------------------------------------------------------------------
// 4) AKG part 1
__global__ void __launch_bounds__(64) k_akgpool(
    const float* __restrict__ F0, const float* __restrict__ F1,
    const float* __restrict__ dwwb, float* __restrict__ dvec)
{
    int gb = blockIdx.x; int r = gb >> 11; int bc = gb & 2047;
    int c = bc & 255;
    const float* P = (r ? F1 : F0) + (size_t)bc * HWHW;
    const float* dww = dwwb + r * CC * 9 + c * 9;
    __shared__ float pool[49];
    __shared__ float cnv[49];
    int t = threadIdx.x;
    if (t < 49) {
        int bi = t / 7, bj = t - bi * 7;
        const float* q = P + bi * 8 * WW + bj * 8;
        float sm = 0.0f;
#pragma unroll
        for (int u = 0; u < 8; ++u)
#pragma unroll
            for (int v = 0; v < 8; ++v) sm += q[u * WW + v];
        pool[t] = sm * 0.015625f;
    }
    __syncthreads();
    if (t < 49) {
        int pi = t / 7, pj = t - pi * 7;
        float sm = 0.0f;
#pragma unroll
        for (int u = 0; u < 3; ++u)
#pragma unroll
            for (int v = 0; v < 3; ++v) {
                int yy = pi + u - 1, xx = pj + v - 1;
                if ((unsigned)yy < 7u && (unsigned)xx < 7u)
                    sm += dww[u * 3 + v] * pool[yy * 7 + xx];
            }
        cnv[t] = fmaxf(sm, 0.0f);
    }
    __syncthreads();
    if (t == 0) {
        float sm = 0.0f;
        for (int i = 0; i < 49; ++i) sm += cnv[i];
        dvec[r * 2048 + bc] = sm * (1.0f / 49.0f);
    }
}

// 5) AKG part 2: 1x1 head (2304x256) + tanh
__global__ void __launch_bounds__(256) k_akghead(
    const float* __restrict__ dvec, const float* __restrict__ hwb,
    const float* __restrict__ hbb, float* __restrict__ Kout)
{
    int b = blockIdx.x, r = blockIdx.y;
    const float* hw = hwb + (size_t)r * 2304 * 256;
    const float* hb = hbb + r * 2304;
    __shared__ float dv[256];
    dv[threadIdx.x] = dvec[r * 2048 + b * 256 + threadIdx.x];
    __syncthreads();
    for (int oc = threadIdx.x; oc < 2304; oc += 256) {
        const float* w = hw + (size_t)oc * 256;
        float sm = hb[oc];
#pragma unroll 8
        for (int c2 = 0; c2 < 256; ++c2) sm += w[c2] * dv[c2];
        Kout[(r * 8 + b) * 2304 + oc] = tanhf(sm);
    }
}

// ---------------------------------------------------------------------------
// 6) dynamic depthwise deformable conv (NHWC gather).
__global__ void __launch_bounds__(256) k_deform(
    const float* __restrict__ F0n, const float* __restrict__ F1n,
    const float* __restrict__ p0, const float* __restrict__ p1,
    const float* __restrict__ Kall, float* __restrict__ D0, float* __restrict__ D1)
{
    int y = blockIdx.x, b = blockIdx.y, r = blockIdx.z;
    const float* Fn = (r ? F1n : F0n) + (size_t)b * HWHW * CC;
    const float* off = (r ? p1 : p0) + (size_t)b * 18 * HWHW;
    const float* Kw = Kall + (r * 8 + b) * 2304;
    float* Dn = (r ? D1 : D0) + (size_t)b * HWHW * CC;

    __shared__ int   sIdx[9][56][4];
    __shared__ float sW[9][56][4];
    __shared__ float sK[9][256];
    int tid = threadIdx.x;
    for (int i = tid; i < 2304; i += 256) {
        int c = i / 9, t = i - c * 9;
        sK[t][c] = Kw[i];
    }
    for (int i = tid; i < 504; i += 256) {
        int t = i / 56, x = i - t * 56;
        int ky = t / 3, kx = t - ky * 3;
        float dy = off[(2 * t) * HWHW + y * WW + x];
        float dx = off[(2 * t + 1) * HWHW + y * WW + x];
        float py = (float)(y + ky - 1) + dy;
        float px = (float)(x + kx - 1) + dx;
        float fy = floorf(py), fx = floorf(px);
        float wy1 = py - fy, wx1 = px - fx;
        float wy0 = 1.0f - wy1, wx0 = 1.0f - wx1;
        int y0 = (int)fy, x0 = (int)fx;
        int y1 = y0 + 1, x1 = x0 + 1;
        bool vy0 = (y0 >= 0) && (y0 < HH);
        bool vy1 = (y1 >= 0) && (y1 < HH);
        bool vx0 = (x0 >= 0) && (x0 < WW);
        bool vx1 = (x1 >= 0) && (x1 < WW);
        int cy0 = min(max(y0, 0), HH - 1), cy1 = min(max(y1, 0), HH - 1);
        int cx0 = min(max(x0, 0), WW - 1), cx1 = min(max(x1, 0), WW - 1);
        sIdx[t][x][0] = (cy0 * WW + cx0) * CC; sW[t][x][0] = (vy0 && vx0) ? wy0 * wx0 : 0.0f;
        sIdx[t][x][1] = (cy0 * WW + cx1) * CC; sW[t][x][1] = (vy0 && vx1) ? wy0 * wx1 : 0.0f;
        sIdx[t][x][2] = (cy1 * WW + cx0) * CC; sW[t][x][2] = (vy1 && vx0) ? wy1 * wx0 : 0.0f;
        sIdx[t][x][3] = (cy1 * WW + cx1) * CC; sW[t][x][3] = (vy1 && vx1) ? wy1 * wx1 : 0.0f;
    }
    __syncthreads();
    int lane = tid & 31, wrp = tid >> 5;   // 8 warps; warp owns x stripe
    for (int x = wrp; x < 56; x += 8) {
        float acc[8];
#pragma unroll
        for (int q = 0; q < 8; ++q) acc[q] = 0.0f;
#pragma unroll
        for (int t = 0; t < 9; ++t) {
            int i0 = sIdx[t][x][0], i1 = sIdx[t][x][1];
            int i2 = sIdx[t][x][2], i3 = sIdx[t][x][3];
            float w0 = sW[t][x][0], w1 = sW[t][x][1];
            float w2 = sW[t][x][2], w3 = sW[t][x][3];
#pragma unroll
            for (int q = 0; q < 8; ++q) {
                int c = q * 32 + lane;
                float v = w0 * Fn[i0 + c] + w1 * Fn[i1 + c]
                        + w2 * Fn[i2 + c] + w3 * Fn[i3 + c];
                acc[q] += sK[t][c] * v;
            }
        }
        float* o = Dn + ((size_t)y * WW + x) * CC;
#pragma unroll
        for (int q = 0; q < 8; ++q) o[q * 32 + lane] = acc[q];
    }
}

// ---------------------------------------------------------------------------
// 7) pw2 1x1 conv over concat(D0,D1) (K=512), NHWC input, NCHW output,
//    with global->register prefetch.
__global__ void __launch_bounds__(128) k_pw2(
    const float* __restrict__ D0, const float* __restrict__ D1,
    const float* __restrict__ wT, const float* __restrict__ bias,
    float* __restrict__ out)
{
    __shared__ __align__(16) float As[8][64];
    __shared__ __align__(16) float Bs[8][132];
    int tid = threadIdx.x;
    int tr = tid >> 4, tcn = tid & 15;
    int px0 = blockIdx.x * 128;
    int ocb = blockIdx.y * 64;
    int mypx = px0 + tid;

    unsigned long long acc2[4][8];
#pragma unroll
    for (int i = 0; i < 4; ++i)
#pragma unroll
        for (int j = 0; j < 8; ++j) acc2[i][j] = 0ULL;

    float4 v0, v1, v0N, v1N;
    float aReg[4], aRegN[4];
    {
        const float* src = D0 + (size_t)mypx * 256;
        v0 = *(const float4*)src;
        v1 = *(const float4*)(src + 4);
#pragma unroll
        for (int j = 0; j < 4; ++j)
            aReg[j] = wT[((tid >> 6) + j * 2) * 256 + ocb + (tid & 63)];
    }

    for (int t = 0; t < 64; ++t) {
        Bs[0][tid] = v0.x; Bs[1][tid] = v0.y; Bs[2][tid] = v0.z; Bs[3][tid] = v0.w;
        Bs[4][tid] = v1.x; Bs[5][tid] = v1.y; Bs[6][tid] = v1.z; Bs[7][tid] = v1.w;
#pragma unroll
        for (int j = 0; j < 4; ++j) {
            int rrow = (tid >> 6) + j * 2;
            As[rrow][tid & 63] = aReg[j];
        }
        __syncthreads();
        if (t + 1 < 64) {
            int k0 = (t + 1) * 8;
            const float* src = (k0 < 256) ? (D0 + (size_t)mypx * 256 + k0)
                                          : (D1 + (size_t)mypx * 256 + (k0 - 256));
            v0N = *(const float4*)src;
            v1N = *(const float4*)(src + 4);
#pragma unroll
            for (int j = 0; j < 4; ++j)
                aRegN[j] = wT[(k0 + (tid >> 6) + j * 2) * 256 + ocb + (tid & 63)];
        }
#pragma unroll
        for (int kk = 0; kk < 8; ++kk) {
            ulonglong2 ua0 = *(const ulonglong2*)&As[kk][tr * 8];
            ulonglong2 ua1 = *(const ulonglong2*)&As[kk][tr * 8 + 4];
            unsigned long long A2[4] = { ua0.x, ua0.y, ua1.x, ua1.y };
            float4 b0 = *(const float4*)&Bs[kk][tcn * 8];
            float4 b1 = *(const float4*)&Bs[kk][tcn * 8 + 4];
            float bv[8] = { b0.x, b0.y, b0.z, b0.w, b1.x, b1.y, b1.z, b1.w };
#pragma unroll
            for (int j = 0; j < 8; ++j) {
                unsigned long long bb = pack2(bv[j], bv[j]);
#pragma unroll
                for (int i2 = 0; i2 < 4; ++i2)
                    acc2[i2][j] = fma_f32x2(A2[i2], bb, acc2[i2][j]);
            }
        }
        __syncthreads();
        v0 = v0N; v1 = v1N;
#pragma unroll
        for (int j = 0; j < 4; ++j) aReg[j] = aRegN[j];
    }

#pragma unroll
    for (int i2 = 0; i2 < 4; ++i2) {
        int oc0 = ocb + tr * 8 + i2 * 2, oc1 = oc0 + 1;
        float bv0 = bias[oc0], bv1 = bias[oc1];
#pragma unroll
        for (int j = 0; j < 8; ++j) {
            float lo, hi; unpack2(acc2[i2][j], lo, hi);
            int px = px0 + tcn * 8 + j;
            int b2 = px / HWHW, s2 = px - b2 * HWHW;
            out[((size_t)b2 * CC + oc0) * HWHW + s2] = lo + bv0;
            out[((size_t)b2 * CC + oc1) * HWHW + s2] = hi + bv1;
        }
    }
}

// ---------------------------------------------------------------------------
// 8) BatchNorm (training-mode batch stats), two deterministic passes
__global__ void __launch_bounds__(256) k_bnred(
    const float* __restrict__ O, const float* __restrict__ gamma,
    const float* __restrict__ beta, float* __restrict__ stat)
{
    int c = blockIdx.x;
    float s = 0.0f, q = 0.0f;
    for (int i = threadIdx.x; i < NPIX; i += 256) {
        int b = i / HWHW, sp = i - b * HWHW;
        float v = O[((size_t)b * CC + c) * HWHW + sp];
        s += v; q += v * v;
    }
    __shared__ float ss[256], qq[256];
    ss[threadIdx.x] = s; qq[threadIdx.x] = q;
    __syncthreads();
    for (int st = 128; st > 0; st >>= 1) {
        if (threadIdx.x < st) {
            ss[threadIdx.x] += ss[threadIdx.x + st];
            qq[threadIdx.x] += qq[threadIdx.x + st];
        }
        __syncthreads();
    }
    if (threadIdx.x == 0) {
        float mean = ss[0] * (1.0f / (float)NPIX);
        float var  = qq[0] * (1.0f / (float)NPIX) - mean * mean;
        float sc = gamma[c] * rsqrtf(var + 1e-5f);
        stat[c] = sc;
        stat[256 + c] = beta[c] - mean * sc;
    }
}

__global__ void k_bnapp(float* __restrict__ O, const float* __restrict__ stat)
{
    int idx = (blockIdx.x * 256 + threadIdx.x) * 2;   // grid covers NF exactly
    float2 v = *(float2*)&O[idx];
    int c = (idx / HWHW) & 255;
    float scl = stat[c], sh = stat[256 + c];
    v.x = v.x * scl + sh;
    v.y = v.y * scl + sh;
    *(float2*)&O[idx] = v;
}

// ---------------------------------------------------------------------------
extern "C" void kernel_launch(void* const* d_in, const int* in_sizes, int n_in,
                              void* d_out, int out_size)
{
    const float* F_c    = (const float*)d_in[0];
    const float* dec_w  = (const float*)d_in[1];
    const float* dec_b  = (const float*)d_in[2];
    const float* off1_w = (const float*)d_in[3];
    const float* off1_b = (const float*)d_in[4];
    const float* off2_w = (const float*)d_in[5];
    const float* off2_b = (const float*)d_in[6];
    const float* akgdw  = (const float*)d_in[7];
    const float* hw     = (const float*)d_in[8];
    const float* hb     = (const float*)d_in[9];
    const float* pw2_w  = (const float*)d_in[10];
    const float* pw2_b  = (const float*)d_in[11];
    const float* gamma  = (const float*)d_in[12];
    const float* beta   = (const float*)d_in[13];
    float* out = (float*)d_out;

    float* sc = nullptr;
    cudaGetSymbolAddress((void**)&sc, g_scratch);

    float* F0   = sc;
    float* F1   = sc + (size_t)NF;
    float* F0n  = sc + (size_t)2 * NF;
    float* F1n  = sc + (size_t)3 * NF;
    float* D0   = sc + (size_t)4 * NF;
    float* D1   = sc + (size_t)5 * NF;
    float* h    = sc + (size_t)6 * NF;        // 2 * 1605632
    float* pp   = h + 3211264;                 // 2 * 451584
    float* wT1  = pp + 903168;                 // 2 * 147456
    float* wT2  = wT1 + 294912;                // 2 * 36864
    float* wTp  = wT2 + 73728;                 // 131072
    float* dvec = wTp + 131072;                // 4096
    float* Kb   = dvec + 4096;                 // 36864
    float* stat = Kb + 36864;                  // 512

    // 1) decouple (+ NHWC copies)
    k_decouple<<<98, 256>>>(F_c, dec_w, dec_b, F0, F1, F0n, F1n);

    // fused weight transposes (wT1 pre-rounded to tf32)
    int wtot = 2 * 2304 * 64 + 2 * 576 * 64 + 512 * 256;
    k_wtrans_all<<<(wtot + 255) / 256, 256>>>(off1_w, off2_w, pw2_w, wT1, wT2, wTp);

    // 2) conv1 via tf32 tensor cores (bias+relu fused), then conv2
    k_conv1t<<<dim3(196, 2), 256>>>(F0, F1, wT1, off1_b, h, h + 1605632);
    k_conv3b<64, 18, 32, 4, false><<<dim3(196, 2), 256>>>(h, h + 1605632, wT2, off2_b, pp, pp + 451584);

    // 4/5) AKG
    k_akgpool<<<4096, 64>>>(F0, F1, akgdw, dvec);
    k_akghead<<<dim3(8, 2), 256>>>(dvec, hw, hb, Kb);

    // 6) deformable dynamic depthwise
    k_deform<<<dim3(56, 8, 2), 256>>>(F0n, F1n, pp, pp + 451584, Kb, D0, D1);

    // 7) pointwise merge -> pre-BN output
    k_pw2<<<dim3(196, 4), 128>>>(D0, D1, wTp, pw2_b, out);

    // 8) BN (training-mode batch stats)
    k_bnred<<<256, 256>>>(out, gamma, beta, stat);
    k_bnapp<<<12544, 256>>>(out, stat);
}